// round 7
// baseline (speedup 1.0000x reference)
#include <cuda_runtime.h>
#include <math_constants.h>
#include <math.h>

#define NN 50000
#define EE 800000
#define BB 64
#define DD 128
#define LL 4
#define HRD 640      /* D*(L+1) */
#define NOUT 10
#define BN_EPS 1e-5

#define TILE_R 128   /* 391 blocks @ 3/SM = one wave (444 slots) */
#define ASTRIDE 132  /* padded smem row stride: rg groups hit distinct banks */
#define RPT (TILE_R / 16)   /* 8 rows per thread */

// ---------------- scratch (device globals; no allocation allowed) ----------
__device__ __align__(16) float  g_hr[(size_t)NN * HRD];   // [x | h1 | h2 | h3 | h4]
__device__ __align__(16) float  g_pooled[NN * DD];
__device__ __align__(16) float  g_z1[NN * DD];
__device__ __align__(16) float  g_z2[NN * DD];
// per-(layer,linear) BN stat slots: [2l] = after mlp_w1, [2l+1] = after mlp_w2
__device__ double g_sumS[2 * LL][DD];
__device__ double g_sumQ[2 * LL][DD];
__device__ float  g_scores[NN];
__device__ __align__(16) float  g_gembp[4 * BB * HRD];    // 4 partials per graph
// CSR scratch. Invariants across calls (graph replays):
//   g_cnt == 0 at call entry (zeroed by scan each call; zero at module load)
//   g_cur is seeded to rowptr by scan each call BEFORE scatter uses it
__device__ int g_cnt[NN];
__device__ int g_cur[NN];
__device__ int g_rowptr[NN + 1];
__device__ int g_esrc[EE];

// ---------------- packed f32x2 helpers (Blackwell) --------------------------
__device__ __forceinline__ void ffma2(unsigned long long& acc,
                                      unsigned long long a,
                                      unsigned long long b) {
    asm("fma.rn.f32x2 %0, %1, %2, %0;" : "+l"(acc) : "l"(a), "l"(b));
}
__device__ __forceinline__ unsigned long long splat2(float a) {
    unsigned long long r;
    asm("mov.b64 %0, {%1, %1};" : "=l"(r) : "f"(a));
    return r;
}
__device__ __forceinline__ float2 unpack2(unsigned long long v) {
    float2 r;
    asm("mov.b64 {%0, %1}, %2;" : "=f"(r.x), "=f"(r.y) : "l"(v));
    return r;
}

// ---------------- CSR construction ------------------------------------------
__global__ void hist_kernel(const int* __restrict__ dst) {
    int e = blockIdx.x * blockDim.x + threadIdx.x;
    if (e < EE) atomicAdd(&g_cnt[dst[e]], 1);
}

// single-block hierarchical scan over 50000 counts.
// Writes rowptr, seeds g_cur = rowptr, zeroes g_cnt, zeroes BN stat slots.
__global__ void __launch_bounds__(1024) scan_kernel() {
    __shared__ int wsum[32];
    __shared__ int carry_sh;
    int tid = threadIdx.x, lane = tid & 31, wid = tid >> 5;
    // zero BN stat slots (deterministic per call -> replay safe)
    for (int i = tid; i < 2 * LL * DD; i += 1024) {
        (&g_sumS[0][0])[i] = 0.0;
        (&g_sumQ[0][0])[i] = 0.0;
    }
    if (tid == 0) carry_sh = 0;
    __syncthreads();
    for (int t = 0; t < 49; t++) {
        int g = t * 1024 + tid;
        int v = (g < NN) ? g_cnt[g] : 0;
        if (g < NN) g_cnt[g] = 0;
        int carry = carry_sh;
        int s = v;
#pragma unroll
        for (int off = 1; off < 32; off <<= 1) {
            int u = __shfl_up_sync(0xffffffffu, s, off);
            if (lane >= off) s += u;
        }
        if (lane == 31) wsum[wid] = s;
        __syncthreads();
        if (wid == 0) {
            int ws = wsum[lane];
#pragma unroll
            for (int off = 1; off < 32; off <<= 1) {
                int u = __shfl_up_sync(0xffffffffu, ws, off);
                if (lane >= off) ws += u;
            }
            wsum[lane] = ws;
        }
        __syncthreads();
        int wpre = (wid == 0) ? 0 : wsum[wid - 1];
        if (g < NN) {
            int rp = carry + wpre + s - v;
            g_rowptr[g] = rp;
            g_cur[g] = rp;          // scatter cursor seeded fresh every call
        }
        __syncthreads();
        if (tid == 1023) carry_sh = carry + wsum[31];
        __syncthreads();
    }
    if (tid == 0) g_rowptr[NN] = EE;
}

__global__ void scatter_kernel(const int* __restrict__ src,
                               const int* __restrict__ dst) {
    int e = blockIdx.x * blockDim.x + threadIdx.x;
    if (e >= EE) return;
    int d = dst[e];
    int p = atomicAdd(&g_cur[d], 1);   // cursor pre-seeded to rowptr[d]
    g_esrc[p] = src[e];
}

// ---------------- aggregation (gather via CSR, high occupancy) ---------------
// pooled[i] = sum_{incoming} h[src] + (1+eps[l])*h[i]
__global__ void aggregate_kernel(const float* __restrict__ x,
                                 const float* __restrict__ eps, int l) {
    int idx = blockIdx.x * blockDim.x + threadIdx.x;
    int i = idx >> 5, lane = idx & 31;
    if (i >= NN) return;
    const float* hsrc = (l == 0) ? x : (g_hr + (size_t)l * DD);
    const int stride = (l == 0) ? DD : HRD;
    int beg = g_rowptr[i], end = g_rowptr[i + 1];
    float4 acc = make_float4(0.f, 0.f, 0.f, 0.f);
    int e = beg;
    for (; e + 3 < end; e += 4) {
        int s0 = g_esrc[e], s1 = g_esrc[e + 1], s2 = g_esrc[e + 2], s3 = g_esrc[e + 3];
        float4 v0 = reinterpret_cast<const float4*>(hsrc + (size_t)s0 * stride)[lane];
        float4 v1 = reinterpret_cast<const float4*>(hsrc + (size_t)s1 * stride)[lane];
        float4 v2 = reinterpret_cast<const float4*>(hsrc + (size_t)s2 * stride)[lane];
        float4 v3 = reinterpret_cast<const float4*>(hsrc + (size_t)s3 * stride)[lane];
        acc.x += (v0.x + v1.x) + (v2.x + v3.x);
        acc.y += (v0.y + v1.y) + (v2.y + v3.y);
        acc.z += (v0.z + v1.z) + (v2.z + v3.z);
        acc.w += (v0.w + v1.w) + (v2.w + v3.w);
    }
    for (; e < end; e++) {
        int s0 = g_esrc[e];
        float4 v0 = reinterpret_cast<const float4*>(hsrc + (size_t)s0 * stride)[lane];
        acc.x += v0.x; acc.y += v0.y; acc.z += v0.z; acc.w += v0.w;
    }
    float sc = 1.0f + eps[l];
    float4 h = reinterpret_cast<const float4*>(hsrc + (size_t)i * stride)[lane];
    acc.x = fmaf(sc, h.x, acc.x);
    acc.y = fmaf(sc, h.y, acc.y);
    acc.z = fmaf(sc, h.z, acc.z);
    acc.w = fmaf(sc, h.w, acc.w);
    reinterpret_cast<float4*>(g_pooled + (size_t)i * DD)[lane] = acc;
}

// ---------------- elementwise / fused score kernels --------------------------
// copy x into hr slab AND initialize scores with x-segment dot
__global__ void copyx_scores_kernel(const float* __restrict__ x,
                                    const float* __restrict__ aw,
                                    const float* __restrict__ ab) {
    int idx = blockIdx.x * blockDim.x + threadIdx.x;
    if (idx >= NN * 32) return;
    int i = idx >> 5, c = idx & 31;
    float4 v = reinterpret_cast<const float4*>(x + (size_t)i * DD)[c];
    reinterpret_cast<float4*>(g_hr + (size_t)i * HRD)[c] = v;
    float4 w = reinterpret_cast<const float4*>(aw)[c];
    float s = v.x * w.x + v.y * w.y + v.z * w.z + v.w * w.w;
#pragma unroll
    for (int off = 16; off; off >>= 1) s += __shfl_down_sync(0xffffffffu, s, off);
    if ((idx & 31) == 0) g_scores[i] = s + ab[0];
}

// h_{l+1} = relu(a*z2 + c) -> hr slab; accumulate score segment.
// Computes BN affine per block from stat slot (2l+1).
__global__ void __launch_bounds__(256) apply_h_kernel(int l,
                                                      const float* __restrict__ aw,
                                                      const float* __restrict__ gamma,
                                                      const float* __restrict__ beta) {
    __shared__ float bnA[DD], bnC[DD];
    int tid = threadIdx.x;
    if (tid < DD) {
        double m = g_sumS[2 * l + 1][tid] / (double)NN;
        double v = g_sumQ[2 * l + 1][tid] / (double)NN - m * m;
        float a = gamma[tid] * rsqrtf((float)(v + (double)BN_EPS));
        bnA[tid] = a;
        bnC[tid] = beta[tid] - (float)m * a;
    }
    __syncthreads();
    int idx = blockIdx.x * blockDim.x + tid;
    if (idx >= NN * 32) return;
    int i = idx >> 5, c = idx & 31;
    float4 z = reinterpret_cast<const float4*>(g_z2 + (size_t)i * DD)[c];
    float4 a = reinterpret_cast<const float4*>(bnA)[c];
    float4 b = reinterpret_cast<const float4*>(bnC)[c];
    float4 o;
    o.x = fmaxf(fmaf(a.x, z.x, b.x), 0.f);
    o.y = fmaxf(fmaf(a.y, z.y, b.y), 0.f);
    o.z = fmaxf(fmaf(a.z, z.z, b.z), 0.f);
    o.w = fmaxf(fmaf(a.w, z.w, b.w), 0.f);
    reinterpret_cast<float4*>(g_hr + (size_t)i * HRD + (size_t)(l + 1) * DD)[c] = o;
    float4 w = reinterpret_cast<const float4*>(aw)[(l + 1) * 32 + c];
    float s = o.x * w.x + o.y * w.y + o.z * w.z + o.w * w.w;
#pragma unroll
    for (int off = 16; off; off >>= 1) s += __shfl_down_sync(0xffffffffu, s, off);
    if ((tid & 31) == 0) g_scores[i] += s;
}

// ---------------- GEMM (128 x 128) @ W[128,128] + b; col stats in fp64 -------
// SECOND=false: A = g_pooled (plain), C = g_z1, stats -> slot 2l
// SECOND=true : A = relu(affine(g_z1)) from slot 2l, C = g_z2, stats -> slot 2l+1
#define GEMM_SMEM (TILE_R * ASTRIDE * 4 + 2 * DD * 8 + 2 * DD * 4)

template <bool SECOND>
__global__ void __launch_bounds__(256, 3) gemm128_kernel(const float* __restrict__ W,
                                                         const float* __restrict__ bias,
                                                         const float* __restrict__ gamma,
                                                         const float* __restrict__ beta,
                                                         int l) {
    extern __shared__ float smem[];
    float* Ash = smem;                                        // TILE_R x ASTRIDE
    double* redS = reinterpret_cast<double*>(smem + TILE_R * ASTRIDE);
    double* redQ = redS + DD;
    float* bnA = reinterpret_cast<float*>(redQ + DD);
    float* bnC = bnA + DD;

    float* C = SECOND ? g_z2 : g_z1;
    const int slot_out = SECOND ? (2 * l + 1) : (2 * l);

    int tid = threadIdx.x;
    if (tid < DD) {
        redS[tid] = 0.0; redQ[tid] = 0.0;
        if (SECOND) {
            double m = g_sumS[2 * l][tid] / (double)NN;
            double v = g_sumQ[2 * l][tid] / (double)NN - m * m;
            float a = gamma[tid] * rsqrtf((float)(v + (double)BN_EPS));
            bnA[tid] = a;
            bnC[tid] = beta[tid] - (float)m * a;
        }
    }
    __syncthreads();

    int row0 = blockIdx.x * TILE_R;
    {
        const float* A = SECOND ? g_z1 : g_pooled;
#pragma unroll
        for (int ii = 0; ii < TILE_R * 32 / 256; ii++) {
            int i = tid + ii * 256;             // float4 index over tile
            int r = i >> 5, c4 = i & 31;
            int row = row0 + r;
            float4 v = make_float4(0.f, 0.f, 0.f, 0.f);
            if (row < NN) {
                v = *reinterpret_cast<const float4*>(A + (size_t)row * DD + c4 * 4);
                if (SECOND) {
                    float4 ba = reinterpret_cast<const float4*>(bnA)[c4];
                    float4 bc = reinterpret_cast<const float4*>(bnC)[c4];
                    v.x = fmaxf(fmaf(ba.x, v.x, bc.x), 0.f);
                    v.y = fmaxf(fmaf(ba.y, v.y, bc.y), 0.f);
                    v.z = fmaxf(fmaf(ba.z, v.z, bc.z), 0.f);
                    v.w = fmaxf(fmaf(ba.w, v.w, bc.w), 0.f);
                }
            }
            *reinterpret_cast<float4*>(Ash + r * ASTRIDE + c4 * 4) = v;
        }
    }
    __syncthreads();

    int cg = tid & 15;   // 8 columns: 8*cg .. 8*cg+7
    int rg = tid >> 4;   // rows rg*RPT .. rg*RPT+RPT-1
    const float* arow = Ash + rg * RPT * ASTRIDE;
    const ulonglong2* Wg = reinterpret_cast<const ulonglong2*>(W);

    unsigned long long acc[RPT][4];
#pragma unroll
    for (int r = 0; r < RPT; r++)
#pragma unroll
        for (int p = 0; p < 4; p++) acc[r][p] = 0ull;

#pragma unroll 2
    for (int k = 0; k < DD; k++) {
        ulonglong2 wA = __ldg(&Wg[k * 32 + cg * 2]);
        ulonglong2 wB = __ldg(&Wg[k * 32 + cg * 2 + 1]);
#pragma unroll
        for (int r = 0; r < RPT; r++) {
            unsigned long long a2 = splat2(arow[r * ASTRIDE + k]);
            ffma2(acc[r][0], a2, wA.x);
            ffma2(acc[r][1], a2, wA.y);
            ffma2(acc[r][2], a2, wB.x);
            ffma2(acc[r][3], a2, wB.y);
        }
    }

    float bs[8];
#pragma unroll
    for (int j = 0; j < 8; j++) bs[j] = bias[cg * 8 + j];

    float cs[8], cq[8];
#pragma unroll
    for (int j = 0; j < 8; j++) { cs[j] = 0.f; cq[j] = 0.f; }

#pragma unroll
    for (int r = 0; r < RPT; r++) {
        int row = row0 + rg * RPT + r;
        if (row >= NN) continue;
        float o[8];
#pragma unroll
        for (int p = 0; p < 4; p++) {
            float2 u = unpack2(acc[r][p]);
            o[2 * p]     = u.x + bs[2 * p];
            o[2 * p + 1] = u.y + bs[2 * p + 1];
        }
        float4* cp = reinterpret_cast<float4*>(C + (size_t)row * DD + cg * 8);
        cp[0] = make_float4(o[0], o[1], o[2], o[3]);
        cp[1] = make_float4(o[4], o[5], o[6], o[7]);
#pragma unroll
        for (int j = 0; j < 8; j++) {
            cs[j] += o[j];
            cq[j] += o[j] * o[j];
        }
    }
    __syncthreads();
#pragma unroll
    for (int j = 0; j < 8; j++) {
        atomicAdd(&redS[cg * 8 + j], (double)cs[j]);
        atomicAdd(&redQ[cg * 8 + j], (double)cq[j]);
    }
    __syncthreads();
    if (tid < DD) {
        atomicAdd(&g_sumS[slot_out][tid], redS[tid]);
        atomicAdd(&g_sumQ[slot_out][tid], redQ[tid]);
    }
}

// ---------------- attention pooling + head ----------------------------------
// 4 blocks per graph; each computes segment max+denom (redundant, cheap) and
// its quarter of the weighted sum. Atomic-free.
#define ECHUNK 512
__global__ void __launch_bounds__(256) gemb_part_kernel(const int* __restrict__ gid) {
    __shared__ int s_beg, s_end;
    __shared__ float red[32];
    __shared__ float s_mx, s_dn;
    __shared__ float ecache[ECHUNK];
    int b = blockIdx.x >> 2, q = blockIdx.x & 3, t = threadIdx.x;
    int lane = t & 31, wid = t >> 5;
    if (t == 0) {
        int lo = 0, hi = NN;
        while (lo < hi) { int m = (lo + hi) >> 1; if (gid[m] < b) lo = m + 1; else hi = m; }
        s_beg = lo;
        lo = 0; hi = NN;
        while (lo < hi) { int m = (lo + hi) >> 1; if (gid[m] < b + 1) lo = m + 1; else hi = m; }
        s_end = lo;
    }
    __syncthreads();
    int beg = s_beg, end = s_end;

    float mx = -CUDART_INF_F;
    for (int i = beg + t; i < end; i += 256) mx = fmaxf(mx, g_scores[i]);
#pragma unroll
    for (int off = 16; off; off >>= 1) mx = fmaxf(mx, __shfl_xor_sync(0xffffffffu, mx, off));
    if (lane == 0) red[wid] = mx;
    __syncthreads();
    if (wid == 0) {
        float m2 = (lane < 8) ? red[lane] : -CUDART_INF_F;
#pragma unroll
        for (int off = 4; off; off >>= 1) m2 = fmaxf(m2, __shfl_xor_sync(0xffffffffu, m2, off));
        if (lane == 0) s_mx = m2;
    }
    __syncthreads();
    float smax = s_mx;

    float dn = 0.f;
    for (int i = beg + t; i < end; i += 256) dn += expf(g_scores[i] - smax);
#pragma unroll
    for (int off = 16; off; off >>= 1) dn += __shfl_xor_sync(0xffffffffu, dn, off);
    if (lane == 0) red[wid] = dn;
    __syncthreads();
    if (wid == 0) {
        float d2 = (lane < 8) ? red[lane] : 0.f;
#pragma unroll
        for (int off = 4; off; off >>= 1) d2 += __shfl_xor_sync(0xffffffffu, d2, off);
        if (lane == 0) s_dn = d2;
    }
    __syncthreads();
    float denom = s_dn;

    int len = end - beg;
    int qb = beg + (int)(((long long)len * q) >> 2);
    int qe = beg + (int)(((long long)len * (q + 1)) >> 2);

    float4 acc = make_float4(0.f, 0.f, 0.f, 0.f);
    for (int chunk = qb; chunk < qe; chunk += ECHUNK) {
        int ce = chunk + ECHUNK < qe ? chunk + ECHUNK : qe;
        for (int i = chunk + t; i < ce; i += 256)
            ecache[i - chunk] = expf(g_scores[i] - smax) / denom;
        __syncthreads();
        if (t < HRD / 4) {
            for (int i = chunk; i < ce; i++) {
                float c = ecache[i - chunk];
                float4 v = reinterpret_cast<const float4*>(g_hr + (size_t)i * HRD)[t];
                acc.x = fmaf(c, v.x, acc.x);
                acc.y = fmaf(c, v.y, acc.y);
                acc.z = fmaf(c, v.z, acc.z);
                acc.w = fmaf(c, v.w, acc.w);
            }
        }
        __syncthreads();
    }
    if (t < HRD / 4)
        reinterpret_cast<float4*>(g_gembp + (size_t)blockIdx.x * HRD)[t] = acc;
}

__global__ void final_kernel(const float* __restrict__ pi,
                             const float* __restrict__ pi_w,
                             const float* __restrict__ pi_b,
                             const float* __restrict__ out_w,
                             const float* __restrict__ out_b,
                             float* __restrict__ out) {
    __shared__ float pie[16];
    int b = blockIdx.x, tid = threadIdx.x;
    if (tid < 16) {
        float a = pi_b[tid];
#pragma unroll
        for (int k = 0; k < 25; k++) a = fmaf(pi[b * 25 + k], pi_w[k * 16 + tid], a);
        pie[tid] = fmaxf(a, 0.f);
    }
    __syncthreads();
    int o = tid >> 5, lane = tid & 31;
    float acc = 0.f;
    const float* g0 = g_gembp + (size_t)(b * 4 + 0) * HRD;
    const float* g1 = g_gembp + (size_t)(b * 4 + 1) * HRD;
    const float* g2 = g_gembp + (size_t)(b * 4 + 2) * HRD;
    const float* g3 = g_gembp + (size_t)(b * 4 + 3) * HRD;
    for (int j = lane; j < HRD; j += 32) {
        float ge = (g0[j] + g1[j]) + (g2[j] + g3[j]);
        acc = fmaf(ge, out_w[j * NOUT + o], acc);
    }
    if (lane < 16) acc = fmaf(pie[lane], out_w[(HRD + lane) * NOUT + o], acc);
#pragma unroll
    for (int off = 16; off; off >>= 1) acc += __shfl_down_sync(0xffffffffu, acc, off);
    if (lane == 0) out[b * NOUT + o] = acc + out_b[o];
}

// ---------------- launch -----------------------------------------------------
extern "C" void kernel_launch(void* const* d_in, const int* in_sizes, int n_in,
                              void* d_out, int out_size) {
    const float* x    = (const float*)d_in[0];
    const float* pi   = (const float*)d_in[1];
    const float* eps  = (const float*)d_in[2];
    const float* w1   = (const float*)d_in[3];
    const float* b1   = (const float*)d_in[4];
    const float* bng1 = (const float*)d_in[5];
    const float* bnb1 = (const float*)d_in[6];
    const float* w2   = (const float*)d_in[7];
    const float* b2   = (const float*)d_in[8];
    const float* bng  = (const float*)d_in[9];
    const float* bnb  = (const float*)d_in[10];
    const float* aw   = (const float*)d_in[11];
    const float* ab   = (const float*)d_in[12];
    const float* pw   = (const float*)d_in[13];
    const float* pb   = (const float*)d_in[14];
    const float* ow   = (const float*)d_in[15];
    const float* ob   = (const float*)d_in[16];
    const int*   ei   = (const int*)d_in[17];
    const int*   gid  = (const int*)d_in[18];
    const int* src = ei;
    const int* dst = ei + EE;
    float* out = (float*)d_out;

    cudaFuncSetAttribute(gemm128_kernel<false>,
                         cudaFuncAttributeMaxDynamicSharedMemorySize, GEMM_SMEM);
    cudaFuncSetAttribute(gemm128_kernel<true>,
                         cudaFuncAttributeMaxDynamicSharedMemorySize, GEMM_SMEM);

    const int ELT_BLOCKS = (NN * 32 + 255) / 256;          // 6250
    const int GEMM_BLOCKS = (NN + TILE_R - 1) / TILE_R;    // 391
    const int EDGE_BLK = (EE + 255) / 256;                 // 3125

    // ---- CSR by dst; g_cnt==0 at entry; scan zeroes stats + seeds cursors ----
    hist_kernel<<<EDGE_BLK, 256>>>(dst);                   // launch 1
    scan_kernel<<<1, 1024>>>();                            // launch 2
    scatter_kernel<<<EDGE_BLK, 256>>>(src, dst);           // launch 3

    for (int l = 0; l < LL; l++) {
        aggregate_kernel<<<ELT_BLOCKS, 256>>>(x, eps, l);  // launch 4 (profiled, l=0)
        if (l == 0) copyx_scores_kernel<<<ELT_BLOCKS, 256>>>(x, aw, ab);
        gemm128_kernel<false><<<GEMM_BLOCKS, 256, GEMM_SMEM>>>(
            w1 + (size_t)l * DD * DD, b1 + l * DD, nullptr, nullptr, l);
        gemm128_kernel<true><<<GEMM_BLOCKS, 256, GEMM_SMEM>>>(
            w2 + (size_t)l * DD * DD, b2 + l * DD, bng1 + l * DD, bnb1 + l * DD, l);
        apply_h_kernel<<<ELT_BLOCKS, 256>>>(l, aw, bng + l * DD, bnb + l * DD);
    }

    gemb_part_kernel<<<4 * BB, 256>>>(gid);
    final_kernel<<<BB, 320>>>(pi, pw, pb, ow, ob, out);
}

// round 8
// speedup vs baseline: 1.1516x; 1.1516x over previous
#include <cuda_runtime.h>
#include <math_constants.h>
#include <math.h>

#define NN 50000
#define EE 800000
#define BB 64
#define DD 128
#define LL 4
#define HRD 640      /* D*(L+1) */
#define NOUT 10
#define BN_EPS 1e-5

#define TILE_R 64    /* 782 blocks @ 4/SM (64-reg budget, RPT=4 -> no spills) */
#define ASTRIDE 132  /* padded smem row stride: rg groups hit distinct banks */
#define RPT (TILE_R / 16)   /* 4 rows per thread */

// ---------------- scratch (device globals; no allocation allowed) ----------
__device__ __align__(16) float  g_hr[(size_t)NN * HRD];   // [x | h1 | h2 | h3 | h4]
__device__ __align__(16) float  g_pooled[NN * DD];
__device__ __align__(16) float  g_z1[NN * DD];
__device__ __align__(16) float  g_z2[NN * DD];
// per-(layer,linear) BN stat slots: [2l] = after mlp_w1, [2l+1] = after mlp_w2
__device__ double g_sumS[2 * LL][DD];
__device__ double g_sumQ[2 * LL][DD];
__device__ float  g_scores[NN];
__device__ __align__(16) float  g_gembp[4 * BB * HRD];    // 4 partials per graph
// CSR scratch. Invariants across calls (graph replays):
//   g_cnt == 0 at call entry (zeroed by scan each call; zero at module load)
//   g_cur is seeded to rowptr by scan each call BEFORE scatter uses it
__device__ int g_cnt[NN];
__device__ int g_cur[NN];
__device__ int g_rowptr[NN + 1];
__device__ int g_esrc[EE];

// ---------------- packed f32x2 helpers (Blackwell) --------------------------
__device__ __forceinline__ void ffma2(unsigned long long& acc,
                                      unsigned long long a,
                                      unsigned long long b) {
    asm("fma.rn.f32x2 %0, %1, %2, %0;" : "+l"(acc) : "l"(a), "l"(b));
}
__device__ __forceinline__ unsigned long long splat2(float a) {
    unsigned long long r;
    asm("mov.b64 %0, {%1, %1};" : "=l"(r) : "f"(a));
    return r;
}
__device__ __forceinline__ float2 unpack2(unsigned long long v) {
    float2 r;
    asm("mov.b64 {%0, %1}, %2;" : "=f"(r.x), "=f"(r.y) : "l"(v));
    return r;
}

// ---------------- CSR construction ------------------------------------------
__global__ void hist_kernel(const int* __restrict__ dst) {
    int e = blockIdx.x * blockDim.x + threadIdx.x;
    if (e < EE) atomicAdd(&g_cnt[dst[e]], 1);
}

// single-block hierarchical scan over 50000 counts.
// Writes rowptr, seeds g_cur = rowptr, zeroes g_cnt, zeroes BN stat slots.
__global__ void __launch_bounds__(1024) scan_kernel() {
    __shared__ int wsum[32];
    __shared__ int carry_sh;
    int tid = threadIdx.x, lane = tid & 31, wid = tid >> 5;
    // zero BN stat slots (deterministic per call -> replay safe)
    for (int i = tid; i < 2 * LL * DD; i += 1024) {
        (&g_sumS[0][0])[i] = 0.0;
        (&g_sumQ[0][0])[i] = 0.0;
    }
    if (tid == 0) carry_sh = 0;
    __syncthreads();
    for (int t = 0; t < 49; t++) {
        int g = t * 1024 + tid;
        int v = (g < NN) ? g_cnt[g] : 0;
        if (g < NN) g_cnt[g] = 0;
        int carry = carry_sh;
        int s = v;
#pragma unroll
        for (int off = 1; off < 32; off <<= 1) {
            int u = __shfl_up_sync(0xffffffffu, s, off);
            if (lane >= off) s += u;
        }
        if (lane == 31) wsum[wid] = s;
        __syncthreads();
        if (wid == 0) {
            int ws = wsum[lane];
#pragma unroll
            for (int off = 1; off < 32; off <<= 1) {
                int u = __shfl_up_sync(0xffffffffu, ws, off);
                if (lane >= off) ws += u;
            }
            wsum[lane] = ws;
        }
        __syncthreads();
        int wpre = (wid == 0) ? 0 : wsum[wid - 1];
        if (g < NN) {
            int rp = carry + wpre + s - v;
            g_rowptr[g] = rp;
            g_cur[g] = rp;          // scatter cursor seeded fresh every call
        }
        __syncthreads();
        if (tid == 1023) carry_sh = carry + wsum[31];
        __syncthreads();
    }
    if (tid == 0) g_rowptr[NN] = EE;
}

__global__ void scatter_kernel(const int* __restrict__ src,
                               const int* __restrict__ dst) {
    int e = blockIdx.x * blockDim.x + threadIdx.x;
    if (e >= EE) return;
    int d = dst[e];
    int p = atomicAdd(&g_cur[d], 1);   // cursor pre-seeded to rowptr[d]
    g_esrc[p] = src[e];
}

// ---------------- aggregation (gather via CSR, high occupancy) ---------------
// pooled[i] = sum_{incoming} h[src] + (1+eps[l])*h[i]
__global__ void aggregate_kernel(const float* __restrict__ x,
                                 const float* __restrict__ eps, int l) {
    int idx = blockIdx.x * blockDim.x + threadIdx.x;
    int i = idx >> 5, lane = idx & 31;
    if (i >= NN) return;
    const float* hsrc = (l == 0) ? x : (g_hr + (size_t)l * DD);
    const int stride = (l == 0) ? DD : HRD;
    int beg = g_rowptr[i], end = g_rowptr[i + 1];
    float4 acc = make_float4(0.f, 0.f, 0.f, 0.f);
    int e = beg;
    for (; e + 3 < end; e += 4) {
        int s0 = g_esrc[e], s1 = g_esrc[e + 1], s2 = g_esrc[e + 2], s3 = g_esrc[e + 3];
        float4 v0 = reinterpret_cast<const float4*>(hsrc + (size_t)s0 * stride)[lane];
        float4 v1 = reinterpret_cast<const float4*>(hsrc + (size_t)s1 * stride)[lane];
        float4 v2 = reinterpret_cast<const float4*>(hsrc + (size_t)s2 * stride)[lane];
        float4 v3 = reinterpret_cast<const float4*>(hsrc + (size_t)s3 * stride)[lane];
        acc.x += (v0.x + v1.x) + (v2.x + v3.x);
        acc.y += (v0.y + v1.y) + (v2.y + v3.y);
        acc.z += (v0.z + v1.z) + (v2.z + v3.z);
        acc.w += (v0.w + v1.w) + (v2.w + v3.w);
    }
    for (; e < end; e++) {
        int s0 = g_esrc[e];
        float4 v0 = reinterpret_cast<const float4*>(hsrc + (size_t)s0 * stride)[lane];
        acc.x += v0.x; acc.y += v0.y; acc.z += v0.z; acc.w += v0.w;
    }
    float sc = 1.0f + eps[l];
    float4 h = reinterpret_cast<const float4*>(hsrc + (size_t)i * stride)[lane];
    acc.x = fmaf(sc, h.x, acc.x);
    acc.y = fmaf(sc, h.y, acc.y);
    acc.z = fmaf(sc, h.z, acc.z);
    acc.w = fmaf(sc, h.w, acc.w);
    reinterpret_cast<float4*>(g_pooled + (size_t)i * DD)[lane] = acc;
}

// ---------------- elementwise / fused score kernels --------------------------
// copy x into hr slab AND initialize scores with x-segment dot
__global__ void copyx_scores_kernel(const float* __restrict__ x,
                                    const float* __restrict__ aw,
                                    const float* __restrict__ ab) {
    int idx = blockIdx.x * blockDim.x + threadIdx.x;
    if (idx >= NN * 32) return;
    int i = idx >> 5, c = idx & 31;
    float4 v = reinterpret_cast<const float4*>(x + (size_t)i * DD)[c];
    reinterpret_cast<float4*>(g_hr + (size_t)i * HRD)[c] = v;
    float4 w = reinterpret_cast<const float4*>(aw)[c];
    float s = v.x * w.x + v.y * w.y + v.z * w.z + v.w * w.w;
#pragma unroll
    for (int off = 16; off; off >>= 1) s += __shfl_down_sync(0xffffffffu, s, off);
    if ((idx & 31) == 0) g_scores[i] = s + ab[0];
}

// h_{l+1} = relu(a*z2 + c) -> hr slab; accumulate score segment.
// Computes BN affine per block from stat slot (2l+1).
__global__ void __launch_bounds__(256) apply_h_kernel(int l,
                                                      const float* __restrict__ aw,
                                                      const float* __restrict__ gamma,
                                                      const float* __restrict__ beta) {
    __shared__ float bnA[DD], bnC[DD];
    int tid = threadIdx.x;
    if (tid < DD) {
        double m = g_sumS[2 * l + 1][tid] / (double)NN;
        double v = g_sumQ[2 * l + 1][tid] / (double)NN - m * m;
        float a = gamma[tid] * rsqrtf((float)(v + (double)BN_EPS));
        bnA[tid] = a;
        bnC[tid] = beta[tid] - (float)m * a;
    }
    __syncthreads();
    int idx = blockIdx.x * blockDim.x + tid;
    if (idx >= NN * 32) return;
    int i = idx >> 5, c = idx & 31;
    float4 z = reinterpret_cast<const float4*>(g_z2 + (size_t)i * DD)[c];
    float4 a = reinterpret_cast<const float4*>(bnA)[c];
    float4 b = reinterpret_cast<const float4*>(bnC)[c];
    float4 o;
    o.x = fmaxf(fmaf(a.x, z.x, b.x), 0.f);
    o.y = fmaxf(fmaf(a.y, z.y, b.y), 0.f);
    o.z = fmaxf(fmaf(a.z, z.z, b.z), 0.f);
    o.w = fmaxf(fmaf(a.w, z.w, b.w), 0.f);
    reinterpret_cast<float4*>(g_hr + (size_t)i * HRD + (size_t)(l + 1) * DD)[c] = o;
    float4 w = reinterpret_cast<const float4*>(aw)[(l + 1) * 32 + c];
    float s = o.x * w.x + o.y * w.y + o.z * w.z + o.w * w.w;
#pragma unroll
    for (int off = 16; off; off >>= 1) s += __shfl_down_sync(0xffffffffu, s, off);
    if ((tid & 31) == 0) g_scores[i] += s;
}

// ---------------- GEMM (64 x 128) @ W[128,128] + b; col stats in fp64 --------
// SECOND=false: A = g_pooled (plain), C = g_z1, stats -> slot 2l
// SECOND=true : A = relu(affine(g_z1)) from slot 2l, C = g_z2, stats -> slot 2l+1
#define GEMM_SMEM (TILE_R * ASTRIDE * 4 + 2 * DD * 8 + 2 * DD * 4)

template <bool SECOND>
__global__ void __launch_bounds__(256, 4) gemm128_kernel(const float* __restrict__ W,
                                                         const float* __restrict__ bias,
                                                         const float* __restrict__ gamma,
                                                         const float* __restrict__ beta,
                                                         int l) {
    extern __shared__ float smem[];
    float* Ash = smem;                                        // TILE_R x ASTRIDE
    double* redS = reinterpret_cast<double*>(smem + TILE_R * ASTRIDE);
    double* redQ = redS + DD;
    float* bnA = reinterpret_cast<float*>(redQ + DD);
    float* bnC = bnA + DD;

    float* C = SECOND ? g_z2 : g_z1;
    const int slot_out = SECOND ? (2 * l + 1) : (2 * l);

    int tid = threadIdx.x;
    if (tid < DD) {
        redS[tid] = 0.0; redQ[tid] = 0.0;
        if (SECOND) {
            double m = g_sumS[2 * l][tid] / (double)NN;
            double v = g_sumQ[2 * l][tid] / (double)NN - m * m;
            float a = gamma[tid] * rsqrtf((float)(v + (double)BN_EPS));
            bnA[tid] = a;
            bnC[tid] = beta[tid] - (float)m * a;
        }
    }
    __syncthreads();

    int row0 = blockIdx.x * TILE_R;
    {
        const float* A = SECOND ? g_z1 : g_pooled;
#pragma unroll
        for (int ii = 0; ii < TILE_R * 32 / 256; ii++) {
            int i = tid + ii * 256;             // float4 index over tile
            int r = i >> 5, c4 = i & 31;
            int row = row0 + r;
            float4 v = make_float4(0.f, 0.f, 0.f, 0.f);
            if (row < NN) {
                v = *reinterpret_cast<const float4*>(A + (size_t)row * DD + c4 * 4);
                if (SECOND) {
                    float4 ba = reinterpret_cast<const float4*>(bnA)[c4];
                    float4 bc = reinterpret_cast<const float4*>(bnC)[c4];
                    v.x = fmaxf(fmaf(ba.x, v.x, bc.x), 0.f);
                    v.y = fmaxf(fmaf(ba.y, v.y, bc.y), 0.f);
                    v.z = fmaxf(fmaf(ba.z, v.z, bc.z), 0.f);
                    v.w = fmaxf(fmaf(ba.w, v.w, bc.w), 0.f);
                }
            }
            *reinterpret_cast<float4*>(Ash + r * ASTRIDE + c4 * 4) = v;
        }
    }
    __syncthreads();

    int cg = tid & 15;   // 8 columns: 8*cg .. 8*cg+7
    int rg = tid >> 4;   // rows rg*RPT .. rg*RPT+RPT-1
    const float* arow = Ash + rg * RPT * ASTRIDE;
    const ulonglong2* Wg = reinterpret_cast<const ulonglong2*>(W);

    unsigned long long acc[RPT][4];
#pragma unroll
    for (int r = 0; r < RPT; r++)
#pragma unroll
        for (int p = 0; p < 4; p++) acc[r][p] = 0ull;

#pragma unroll 4
    for (int k = 0; k < DD; k++) {
        ulonglong2 wA = __ldg(&Wg[k * 32 + cg * 2]);
        ulonglong2 wB = __ldg(&Wg[k * 32 + cg * 2 + 1]);
#pragma unroll
        for (int r = 0; r < RPT; r++) {
            unsigned long long a2 = splat2(arow[r * ASTRIDE + k]);
            ffma2(acc[r][0], a2, wA.x);
            ffma2(acc[r][1], a2, wA.y);
            ffma2(acc[r][2], a2, wB.x);
            ffma2(acc[r][3], a2, wB.y);
        }
    }

    float bs[8];
#pragma unroll
    for (int j = 0; j < 8; j++) bs[j] = bias[cg * 8 + j];

    float cs[8], cq[8];
#pragma unroll
    for (int j = 0; j < 8; j++) { cs[j] = 0.f; cq[j] = 0.f; }

#pragma unroll
    for (int r = 0; r < RPT; r++) {
        int row = row0 + rg * RPT + r;
        if (row >= NN) continue;
        float o[8];
#pragma unroll
        for (int p = 0; p < 4; p++) {
            float2 u = unpack2(acc[r][p]);
            o[2 * p]     = u.x + bs[2 * p];
            o[2 * p + 1] = u.y + bs[2 * p + 1];
        }
        float4* cp = reinterpret_cast<float4*>(C + (size_t)row * DD + cg * 8);
        cp[0] = make_float4(o[0], o[1], o[2], o[3]);
        cp[1] = make_float4(o[4], o[5], o[6], o[7]);
#pragma unroll
        for (int j = 0; j < 8; j++) {
            cs[j] += o[j];
            cq[j] += o[j] * o[j];
        }
    }
    __syncthreads();
#pragma unroll
    for (int j = 0; j < 8; j++) {
        atomicAdd(&redS[cg * 8 + j], (double)cs[j]);
        atomicAdd(&redQ[cg * 8 + j], (double)cq[j]);
    }
    __syncthreads();
    if (tid < DD) {
        atomicAdd(&g_sumS[slot_out][tid], redS[tid]);
        atomicAdd(&g_sumQ[slot_out][tid], redQ[tid]);
    }
}

// ---------------- attention pooling + head ----------------------------------
// 4 blocks per graph; each computes segment max+denom (redundant, cheap) and
// its quarter of the weighted sum. Atomic-free.
#define ECHUNK 512
__global__ void __launch_bounds__(256) gemb_part_kernel(const int* __restrict__ gid) {
    __shared__ int s_beg, s_end;
    __shared__ float red[32];
    __shared__ float s_mx, s_dn;
    __shared__ float ecache[ECHUNK];
    int b = blockIdx.x >> 2, q = blockIdx.x & 3, t = threadIdx.x;
    int lane = t & 31, wid = t >> 5;
    if (t == 0) {
        int lo = 0, hi = NN;
        while (lo < hi) { int m = (lo + hi) >> 1; if (gid[m] < b) lo = m + 1; else hi = m; }
        s_beg = lo;
        lo = 0; hi = NN;
        while (lo < hi) { int m = (lo + hi) >> 1; if (gid[m] < b + 1) lo = m + 1; else hi = m; }
        s_end = lo;
    }
    __syncthreads();
    int beg = s_beg, end = s_end;

    float mx = -CUDART_INF_F;
    for (int i = beg + t; i < end; i += 256) mx = fmaxf(mx, g_scores[i]);
#pragma unroll
    for (int off = 16; off; off >>= 1) mx = fmaxf(mx, __shfl_xor_sync(0xffffffffu, mx, off));
    if (lane == 0) red[wid] = mx;
    __syncthreads();
    if (wid == 0) {
        float m2 = (lane < 8) ? red[lane] : -CUDART_INF_F;
#pragma unroll
        for (int off = 4; off; off >>= 1) m2 = fmaxf(m2, __shfl_xor_sync(0xffffffffu, m2, off));
        if (lane == 0) s_mx = m2;
    }
    __syncthreads();
    float smax = s_mx;

    float dn = 0.f;
    for (int i = beg + t; i < end; i += 256) dn += expf(g_scores[i] - smax);
#pragma unroll
    for (int off = 16; off; off >>= 1) dn += __shfl_xor_sync(0xffffffffu, dn, off);
    if (lane == 0) red[wid] = dn;
    __syncthreads();
    if (wid == 0) {
        float d2 = (lane < 8) ? red[lane] : 0.f;
#pragma unroll
        for (int off = 4; off; off >>= 1) d2 += __shfl_xor_sync(0xffffffffu, d2, off);
        if (lane == 0) s_dn = d2;
    }
    __syncthreads();
    float denom = s_dn;

    int len = end - beg;
    int qb = beg + (int)(((long long)len * q) >> 2);
    int qe = beg + (int)(((long long)len * (q + 1)) >> 2);

    float4 acc = make_float4(0.f, 0.f, 0.f, 0.f);
    for (int chunk = qb; chunk < qe; chunk += ECHUNK) {
        int ce = chunk + ECHUNK < qe ? chunk + ECHUNK : qe;
        for (int i = chunk + t; i < ce; i += 256)
            ecache[i - chunk] = expf(g_scores[i] - smax) / denom;
        __syncthreads();
        if (t < HRD / 4) {
            for (int i = chunk; i < ce; i++) {
                float c = ecache[i - chunk];
                float4 v = reinterpret_cast<const float4*>(g_hr + (size_t)i * HRD)[t];
                acc.x = fmaf(c, v.x, acc.x);
                acc.y = fmaf(c, v.y, acc.y);
                acc.z = fmaf(c, v.z, acc.z);
                acc.w = fmaf(c, v.w, acc.w);
            }
        }
        __syncthreads();
    }
    if (t < HRD / 4)
        reinterpret_cast<float4*>(g_gembp + (size_t)blockIdx.x * HRD)[t] = acc;
}

__global__ void final_kernel(const float* __restrict__ pi,
                             const float* __restrict__ pi_w,
                             const float* __restrict__ pi_b,
                             const float* __restrict__ out_w,
                             const float* __restrict__ out_b,
                             float* __restrict__ out) {
    __shared__ float pie[16];
    int b = blockIdx.x, tid = threadIdx.x;
    if (tid < 16) {
        float a = pi_b[tid];
#pragma unroll
        for (int k = 0; k < 25; k++) a = fmaf(pi[b * 25 + k], pi_w[k * 16 + tid], a);
        pie[tid] = fmaxf(a, 0.f);
    }
    __syncthreads();
    int o = tid >> 5, lane = tid & 31;
    float acc = 0.f;
    const float* g0 = g_gembp + (size_t)(b * 4 + 0) * HRD;
    const float* g1 = g_gembp + (size_t)(b * 4 + 1) * HRD;
    const float* g2 = g_gembp + (size_t)(b * 4 + 2) * HRD;
    const float* g3 = g_gembp + (size_t)(b * 4 + 3) * HRD;
    for (int j = lane; j < HRD; j += 32) {
        float ge = (g0[j] + g1[j]) + (g2[j] + g3[j]);
        acc = fmaf(ge, out_w[j * NOUT + o], acc);
    }
    if (lane < 16) acc = fmaf(pie[lane], out_w[(HRD + lane) * NOUT + o], acc);
#pragma unroll
    for (int off = 16; off; off >>= 1) acc += __shfl_down_sync(0xffffffffu, acc, off);
    if (lane == 0) out[b * NOUT + o] = acc + out_b[o];
}

// ---------------- launch -----------------------------------------------------
extern "C" void kernel_launch(void* const* d_in, const int* in_sizes, int n_in,
                              void* d_out, int out_size) {
    const float* x    = (const float*)d_in[0];
    const float* pi   = (const float*)d_in[1];
    const float* eps  = (const float*)d_in[2];
    const float* w1   = (const float*)d_in[3];
    const float* b1   = (const float*)d_in[4];
    const float* bng1 = (const float*)d_in[5];
    const float* bnb1 = (const float*)d_in[6];
    const float* w2   = (const float*)d_in[7];
    const float* b2   = (const float*)d_in[8];
    const float* bng  = (const float*)d_in[9];
    const float* bnb  = (const float*)d_in[10];
    const float* aw   = (const float*)d_in[11];
    const float* ab   = (const float*)d_in[12];
    const float* pw   = (const float*)d_in[13];
    const float* pb   = (const float*)d_in[14];
    const float* ow   = (const float*)d_in[15];
    const float* ob   = (const float*)d_in[16];
    const int*   ei   = (const int*)d_in[17];
    const int*   gid  = (const int*)d_in[18];
    const int* src = ei;
    const int* dst = ei + EE;
    float* out = (float*)d_out;

    cudaFuncSetAttribute(gemm128_kernel<false>,
                         cudaFuncAttributeMaxDynamicSharedMemorySize, GEMM_SMEM);
    cudaFuncSetAttribute(gemm128_kernel<true>,
                         cudaFuncAttributeMaxDynamicSharedMemorySize, GEMM_SMEM);

    const int ELT_BLOCKS = (NN * 32 + 255) / 256;          // 6250
    const int GEMM_BLOCKS = (NN + TILE_R - 1) / TILE_R;    // 782
    const int EDGE_BLK = (EE + 255) / 256;                 // 3125

    // ---- CSR by dst; g_cnt==0 at entry; scan zeroes stats + seeds cursors ----
    hist_kernel<<<EDGE_BLK, 256>>>(dst);                   // launch 1
    scan_kernel<<<1, 1024>>>();                            // launch 2
    scatter_kernel<<<EDGE_BLK, 256>>>(src, dst);           // launch 3

    for (int l = 0; l < LL; l++) {
        aggregate_kernel<<<ELT_BLOCKS, 256>>>(x, eps, l);
        if (l == 0) copyx_scores_kernel<<<ELT_BLOCKS, 256>>>(x, aw, ab);
        gemm128_kernel<false><<<GEMM_BLOCKS, 256, GEMM_SMEM>>>(   // launch 5/6 = profiled
            w1 + (size_t)l * DD * DD, b1 + l * DD, nullptr, nullptr, l);
        gemm128_kernel<true><<<GEMM_BLOCKS, 256, GEMM_SMEM>>>(
            w2 + (size_t)l * DD * DD, b2 + l * DD, bng1 + l * DD, bnb1 + l * DD, l);
        apply_h_kernel<<<ELT_BLOCKS, 256>>>(l, aw, bng + l * DD, bnb + l * DD);
    }

    gemb_part_kernel<<<4 * BB, 256>>>(gid);
    final_kernel<<<BB, 320>>>(pi, pw, pb, ow, ob, out);
}

// round 9
// speedup vs baseline: 1.5834x; 1.3750x over previous
#include <cuda_runtime.h>
#include <math_constants.h>
#include <math.h>

#define NN 50000
#define EE 800000
#define BB 64
#define DD 128
#define LL 4
#define HRD 640      /* D*(L+1) */
#define NOUT 10
#define BN_EPS 1e-5

#define TILE_R 160   /* 313 blocks @ 2/SM = 1.06 waves; 128-reg family (no spills) */
#define ASTRIDE 132  /* padded smem row stride: rg groups hit distinct banks */
#define RPT (TILE_R / 16)   /* 10 rows per thread */

// ---------------- scratch (device globals; no allocation allowed) ----------
__device__ __align__(16) float  g_hr[(size_t)NN * HRD];   // [x | h1 | h2 | h3 | h4]
__device__ __align__(16) float  g_pooled[NN * DD];
__device__ __align__(16) float  g_z1[NN * DD];
__device__ __align__(16) float  g_z2[NN * DD];
// per-(layer,linear) BN stat slots: [2l] = after mlp_w1, [2l+1] = after mlp_w2
__device__ double g_sumS[2 * LL][DD];
__device__ double g_sumQ[2 * LL][DD];
__device__ float  g_scores[NN];
__device__ __align__(16) float  g_gembp[4 * BB * HRD];    // 4 partials per graph
// CSR scratch. Invariants across calls (graph replays):
//   g_cnt == 0 at call entry (zeroed by scan each call; zero at module load)
//   g_cur is seeded to rowptr by scan each call BEFORE scatter uses it
__device__ int g_cnt[NN];
__device__ int g_cur[NN];
__device__ int g_rowptr[NN + 1];
__device__ int g_esrc[EE];

// ---------------- packed f32x2 helpers (Blackwell) --------------------------
__device__ __forceinline__ void ffma2(unsigned long long& acc,
                                      unsigned long long a,
                                      unsigned long long b) {
    asm("fma.rn.f32x2 %0, %1, %2, %0;" : "+l"(acc) : "l"(a), "l"(b));
}
__device__ __forceinline__ unsigned long long splat2(float a) {
    unsigned long long r;
    asm("mov.b64 %0, {%1, %1};" : "=l"(r) : "f"(a));
    return r;
}
__device__ __forceinline__ float2 unpack2(unsigned long long v) {
    float2 r;
    asm("mov.b64 {%0, %1}, %2;" : "=f"(r.x), "=f"(r.y) : "l"(v));
    return r;
}

// ---------------- CSR construction ------------------------------------------
__global__ void hist_kernel(const int* __restrict__ dst) {
    int e = blockIdx.x * blockDim.x + threadIdx.x;
    if (e < EE) atomicAdd(&g_cnt[dst[e]], 1);
}

// single-block hierarchical scan over 50000 counts.
// Writes rowptr, seeds g_cur = rowptr, zeroes g_cnt, zeroes BN stat slots.
__global__ void __launch_bounds__(1024) scan_kernel() {
    __shared__ int wsum[32];
    __shared__ int carry_sh;
    int tid = threadIdx.x, lane = tid & 31, wid = tid >> 5;
    // zero BN stat slots (deterministic per call -> replay safe)
    for (int i = tid; i < 2 * LL * DD; i += 1024) {
        (&g_sumS[0][0])[i] = 0.0;
        (&g_sumQ[0][0])[i] = 0.0;
    }
    if (tid == 0) carry_sh = 0;
    __syncthreads();
    for (int t = 0; t < 49; t++) {
        int g = t * 1024 + tid;
        int v = (g < NN) ? g_cnt[g] : 0;
        if (g < NN) g_cnt[g] = 0;
        int carry = carry_sh;
        int s = v;
#pragma unroll
        for (int off = 1; off < 32; off <<= 1) {
            int u = __shfl_up_sync(0xffffffffu, s, off);
            if (lane >= off) s += u;
        }
        if (lane == 31) wsum[wid] = s;
        __syncthreads();
        if (wid == 0) {
            int ws = wsum[lane];
#pragma unroll
            for (int off = 1; off < 32; off <<= 1) {
                int u = __shfl_up_sync(0xffffffffu, ws, off);
                if (lane >= off) ws += u;
            }
            wsum[lane] = ws;
        }
        __syncthreads();
        int wpre = (wid == 0) ? 0 : wsum[wid - 1];
        if (g < NN) {
            int rp = carry + wpre + s - v;
            g_rowptr[g] = rp;
            g_cur[g] = rp;          // scatter cursor seeded fresh every call
        }
        __syncthreads();
        if (tid == 1023) carry_sh = carry + wsum[31];
        __syncthreads();
    }
    if (tid == 0) g_rowptr[NN] = EE;
}

__global__ void scatter_kernel(const int* __restrict__ src,
                               const int* __restrict__ dst) {
    int e = blockIdx.x * blockDim.x + threadIdx.x;
    if (e >= EE) return;
    int d = dst[e];
    int p = atomicAdd(&g_cur[d], 1);   // cursor pre-seeded to rowptr[d]
    g_esrc[p] = src[e];
}

// ---------------- aggregation (gather via CSR, high occupancy) ---------------
// pooled[i] = sum_{incoming} h[src] + (1+eps[l])*h[i]
__global__ void aggregate_kernel(const float* __restrict__ x,
                                 const float* __restrict__ eps, int l) {
    int idx = blockIdx.x * blockDim.x + threadIdx.x;
    int i = idx >> 5, lane = idx & 31;
    if (i >= NN) return;
    const float* hsrc = (l == 0) ? x : (g_hr + (size_t)l * DD);
    const int stride = (l == 0) ? DD : HRD;
    int beg = g_rowptr[i], end = g_rowptr[i + 1];
    float4 acc = make_float4(0.f, 0.f, 0.f, 0.f);
    int e = beg;
    for (; e + 3 < end; e += 4) {
        int s0 = g_esrc[e], s1 = g_esrc[e + 1], s2 = g_esrc[e + 2], s3 = g_esrc[e + 3];
        float4 v0 = reinterpret_cast<const float4*>(hsrc + (size_t)s0 * stride)[lane];
        float4 v1 = reinterpret_cast<const float4*>(hsrc + (size_t)s1 * stride)[lane];
        float4 v2 = reinterpret_cast<const float4*>(hsrc + (size_t)s2 * stride)[lane];
        float4 v3 = reinterpret_cast<const float4*>(hsrc + (size_t)s3 * stride)[lane];
        acc.x += (v0.x + v1.x) + (v2.x + v3.x);
        acc.y += (v0.y + v1.y) + (v2.y + v3.y);
        acc.z += (v0.z + v1.z) + (v2.z + v3.z);
        acc.w += (v0.w + v1.w) + (v2.w + v3.w);
    }
    for (; e < end; e++) {
        int s0 = g_esrc[e];
        float4 v0 = reinterpret_cast<const float4*>(hsrc + (size_t)s0 * stride)[lane];
        acc.x += v0.x; acc.y += v0.y; acc.z += v0.z; acc.w += v0.w;
    }
    float sc = 1.0f + eps[l];
    float4 h = reinterpret_cast<const float4*>(hsrc + (size_t)i * stride)[lane];
    acc.x = fmaf(sc, h.x, acc.x);
    acc.y = fmaf(sc, h.y, acc.y);
    acc.z = fmaf(sc, h.z, acc.z);
    acc.w = fmaf(sc, h.w, acc.w);
    reinterpret_cast<float4*>(g_pooled + (size_t)i * DD)[lane] = acc;
}

// ---------------- elementwise / fused score kernels --------------------------
// copy x into hr slab AND initialize scores with x-segment dot
__global__ void copyx_scores_kernel(const float* __restrict__ x,
                                    const float* __restrict__ aw,
                                    const float* __restrict__ ab) {
    int idx = blockIdx.x * blockDim.x + threadIdx.x;
    if (idx >= NN * 32) return;
    int i = idx >> 5, c = idx & 31;
    float4 v = reinterpret_cast<const float4*>(x + (size_t)i * DD)[c];
    reinterpret_cast<float4*>(g_hr + (size_t)i * HRD)[c] = v;
    float4 w = reinterpret_cast<const float4*>(aw)[c];
    float s = v.x * w.x + v.y * w.y + v.z * w.z + v.w * w.w;
#pragma unroll
    for (int off = 16; off; off >>= 1) s += __shfl_down_sync(0xffffffffu, s, off);
    if ((idx & 31) == 0) g_scores[i] = s + ab[0];
}

// h_{l+1} = relu(a*z2 + c) -> hr slab; accumulate score segment.
// Computes BN affine per block from stat slot (2l+1).
__global__ void __launch_bounds__(256) apply_h_kernel(int l,
                                                      const float* __restrict__ aw,
                                                      const float* __restrict__ gamma,
                                                      const float* __restrict__ beta) {
    __shared__ float bnA[DD], bnC[DD];
    int tid = threadIdx.x;
    if (tid < DD) {
        double m = g_sumS[2 * l + 1][tid] / (double)NN;
        double v = g_sumQ[2 * l + 1][tid] / (double)NN - m * m;
        float a = gamma[tid] * rsqrtf((float)(v + (double)BN_EPS));
        bnA[tid] = a;
        bnC[tid] = beta[tid] - (float)m * a;
    }
    __syncthreads();
    int idx = blockIdx.x * blockDim.x + tid;
    if (idx >= NN * 32) return;
    int i = idx >> 5, c = idx & 31;
    float4 z = reinterpret_cast<const float4*>(g_z2 + (size_t)i * DD)[c];
    float4 a = reinterpret_cast<const float4*>(bnA)[c];
    float4 b = reinterpret_cast<const float4*>(bnC)[c];
    float4 o;
    o.x = fmaxf(fmaf(a.x, z.x, b.x), 0.f);
    o.y = fmaxf(fmaf(a.y, z.y, b.y), 0.f);
    o.z = fmaxf(fmaf(a.z, z.z, b.z), 0.f);
    o.w = fmaxf(fmaf(a.w, z.w, b.w), 0.f);
    reinterpret_cast<float4*>(g_hr + (size_t)i * HRD + (size_t)(l + 1) * DD)[c] = o;
    float4 w = reinterpret_cast<const float4*>(aw)[(l + 1) * 32 + c];
    float s = o.x * w.x + o.y * w.y + o.z * w.z + o.w * w.w;
#pragma unroll
    for (int off = 16; off; off >>= 1) s += __shfl_down_sync(0xffffffffu, s, off);
    if ((tid & 31) == 0) g_scores[i] += s;
}

// ---------------- GEMM (160 x 128) @ W[128,128] + b; col stats in fp64 -------
// SECOND=false: A = g_pooled (plain), C = g_z1, stats -> slot 2l
// SECOND=true : A = relu(affine(g_z1)) from slot 2l, C = g_z2, stats -> slot 2l+1
#define GEMM_SMEM (TILE_R * ASTRIDE * 4 + 2 * DD * 8 + 2 * DD * 4)

template <bool SECOND>
__global__ void __launch_bounds__(256, 2) gemm128_kernel(const float* __restrict__ W,
                                                         const float* __restrict__ bias,
                                                         const float* __restrict__ gamma,
                                                         const float* __restrict__ beta,
                                                         int l) {
    extern __shared__ float smem[];
    float* Ash = smem;                                        // TILE_R x ASTRIDE
    double* redS = reinterpret_cast<double*>(smem + TILE_R * ASTRIDE);
    double* redQ = redS + DD;
    float* bnA = reinterpret_cast<float*>(redQ + DD);
    float* bnC = bnA + DD;

    float* C = SECOND ? g_z2 : g_z1;
    const int slot_out = SECOND ? (2 * l + 1) : (2 * l);

    int tid = threadIdx.x;
    if (tid < DD) {
        redS[tid] = 0.0; redQ[tid] = 0.0;
        if (SECOND) {
            double m = g_sumS[2 * l][tid] / (double)NN;
            double v = g_sumQ[2 * l][tid] / (double)NN - m * m;
            float a = gamma[tid] * rsqrtf((float)(v + (double)BN_EPS));
            bnA[tid] = a;
            bnC[tid] = beta[tid] - (float)m * a;
        }
    }
    __syncthreads();

    int row0 = blockIdx.x * TILE_R;
    {
        const float* A = SECOND ? g_z1 : g_pooled;
#pragma unroll
        for (int ii = 0; ii < TILE_R * 32 / 256; ii++) {
            int i = tid + ii * 256;             // float4 index over tile
            int r = i >> 5, c4 = i & 31;
            int row = row0 + r;
            float4 v = make_float4(0.f, 0.f, 0.f, 0.f);
            if (row < NN) {
                v = *reinterpret_cast<const float4*>(A + (size_t)row * DD + c4 * 4);
                if (SECOND) {
                    float4 ba = reinterpret_cast<const float4*>(bnA)[c4];
                    float4 bc = reinterpret_cast<const float4*>(bnC)[c4];
                    v.x = fmaxf(fmaf(ba.x, v.x, bc.x), 0.f);
                    v.y = fmaxf(fmaf(ba.y, v.y, bc.y), 0.f);
                    v.z = fmaxf(fmaf(ba.z, v.z, bc.z), 0.f);
                    v.w = fmaxf(fmaf(ba.w, v.w, bc.w), 0.f);
                }
            }
            *reinterpret_cast<float4*>(Ash + r * ASTRIDE + c4 * 4) = v;
        }
    }
    __syncthreads();

    int cg = tid & 15;   // 8 columns: 8*cg .. 8*cg+7
    int rg = tid >> 4;   // rows rg*RPT .. rg*RPT+RPT-1
    const float2* arow2 = reinterpret_cast<const float2*>(Ash + rg * RPT * ASTRIDE);
    const ulonglong2* Wg = reinterpret_cast<const ulonglong2*>(W);

    unsigned long long acc[RPT][4];
#pragma unroll
    for (int r = 0; r < RPT; r++)
#pragma unroll
        for (int p = 0; p < 4; p++) acc[r][p] = 0ull;

    // mainloop: 2 k's per iteration, LDS.64 A loads, 16 FFMA2 per row-pair-k
#pragma unroll 1
    for (int k2 = 0; k2 < DD / 2; k2++) {
        ulonglong2 w0A = __ldg(&Wg[(2 * k2) * 32 + cg * 2]);
        ulonglong2 w0B = __ldg(&Wg[(2 * k2) * 32 + cg * 2 + 1]);
        ulonglong2 w1A = __ldg(&Wg[(2 * k2 + 1) * 32 + cg * 2]);
        ulonglong2 w1B = __ldg(&Wg[(2 * k2 + 1) * 32 + cg * 2 + 1]);
#pragma unroll
        for (int r = 0; r < RPT; r++) {
            float2 a2 = arow2[r * (ASTRIDE / 2) + k2];
            unsigned long long s0 = splat2(a2.x);
            unsigned long long s1 = splat2(a2.y);
            ffma2(acc[r][0], s0, w0A.x);
            ffma2(acc[r][1], s0, w0A.y);
            ffma2(acc[r][2], s0, w0B.x);
            ffma2(acc[r][3], s0, w0B.y);
            ffma2(acc[r][0], s1, w1A.x);
            ffma2(acc[r][1], s1, w1A.y);
            ffma2(acc[r][2], s1, w1B.x);
            ffma2(acc[r][3], s1, w1B.y);
        }
    }

    float bs[8];
#pragma unroll
    for (int j = 0; j < 8; j++) bs[j] = bias[cg * 8 + j];

    float cs[8], cq[8];
#pragma unroll
    for (int j = 0; j < 8; j++) { cs[j] = 0.f; cq[j] = 0.f; }

#pragma unroll
    for (int r = 0; r < RPT; r++) {
        int row = row0 + rg * RPT + r;
        if (row >= NN) continue;
        float o[8];
#pragma unroll
        for (int p = 0; p < 4; p++) {
            float2 u = unpack2(acc[r][p]);
            o[2 * p]     = u.x + bs[2 * p];
            o[2 * p + 1] = u.y + bs[2 * p + 1];
        }
        float4* cp = reinterpret_cast<float4*>(C + (size_t)row * DD + cg * 8);
        cp[0] = make_float4(o[0], o[1], o[2], o[3]);
        cp[1] = make_float4(o[4], o[5], o[6], o[7]);
#pragma unroll
        for (int j = 0; j < 8; j++) {
            cs[j] += o[j];
            cq[j] += o[j] * o[j];
        }
    }
    __syncthreads();
#pragma unroll
    for (int j = 0; j < 8; j++) {
        atomicAdd(&redS[cg * 8 + j], (double)cs[j]);
        atomicAdd(&redQ[cg * 8 + j], (double)cq[j]);
    }
    __syncthreads();
    if (tid < DD) {
        atomicAdd(&g_sumS[slot_out][tid], redS[tid]);
        atomicAdd(&g_sumQ[slot_out][tid], redQ[tid]);
    }
}

// ---------------- attention pooling + head ----------------------------------
// 4 blocks per graph; each computes segment max+denom (redundant, cheap) and
// its quarter of the weighted sum. Atomic-free.
#define ECHUNK 512
__global__ void __launch_bounds__(256) gemb_part_kernel(const int* __restrict__ gid) {
    __shared__ int s_beg, s_end;
    __shared__ float red[32];
    __shared__ float s_mx, s_dn;
    __shared__ float ecache[ECHUNK];
    int b = blockIdx.x >> 2, q = blockIdx.x & 3, t = threadIdx.x;
    int lane = t & 31, wid = t >> 5;
    if (t == 0) {
        int lo = 0, hi = NN;
        while (lo < hi) { int m = (lo + hi) >> 1; if (gid[m] < b) lo = m + 1; else hi = m; }
        s_beg = lo;
        lo = 0; hi = NN;
        while (lo < hi) { int m = (lo + hi) >> 1; if (gid[m] < b + 1) lo = m + 1; else hi = m; }
        s_end = lo;
    }
    __syncthreads();
    int beg = s_beg, end = s_end;

    float mx = -CUDART_INF_F;
    for (int i = beg + t; i < end; i += 256) mx = fmaxf(mx, g_scores[i]);
#pragma unroll
    for (int off = 16; off; off >>= 1) mx = fmaxf(mx, __shfl_xor_sync(0xffffffffu, mx, off));
    if (lane == 0) red[wid] = mx;
    __syncthreads();
    if (wid == 0) {
        float m2 = (lane < 8) ? red[lane] : -CUDART_INF_F;
#pragma unroll
        for (int off = 4; off; off >>= 1) m2 = fmaxf(m2, __shfl_xor_sync(0xffffffffu, m2, off));
        if (lane == 0) s_mx = m2;
    }
    __syncthreads();
    float smax = s_mx;

    float dn = 0.f;
    for (int i = beg + t; i < end; i += 256) dn += expf(g_scores[i] - smax);
#pragma unroll
    for (int off = 16; off; off >>= 1) dn += __shfl_xor_sync(0xffffffffu, dn, off);
    if (lane == 0) red[wid] = dn;
    __syncthreads();
    if (wid == 0) {
        float d2 = (lane < 8) ? red[lane] : 0.f;
#pragma unroll
        for (int off = 4; off; off >>= 1) d2 += __shfl_xor_sync(0xffffffffu, d2, off);
        if (lane == 0) s_dn = d2;
    }
    __syncthreads();
    float denom = s_dn;

    int len = end - beg;
    int qb = beg + (int)(((long long)len * q) >> 2);
    int qe = beg + (int)(((long long)len * (q + 1)) >> 2);

    float4 acc = make_float4(0.f, 0.f, 0.f, 0.f);
    for (int chunk = qb; chunk < qe; chunk += ECHUNK) {
        int ce = chunk + ECHUNK < qe ? chunk + ECHUNK : qe;
        for (int i = chunk + t; i < ce; i += 256)
            ecache[i - chunk] = expf(g_scores[i] - smax) / denom;
        __syncthreads();
        if (t < HRD / 4) {
            for (int i = chunk; i < ce; i++) {
                float c = ecache[i - chunk];
                float4 v = reinterpret_cast<const float4*>(g_hr + (size_t)i * HRD)[t];
                acc.x = fmaf(c, v.x, acc.x);
                acc.y = fmaf(c, v.y, acc.y);
                acc.z = fmaf(c, v.z, acc.z);
                acc.w = fmaf(c, v.w, acc.w);
            }
        }
        __syncthreads();
    }
    if (t < HRD / 4)
        reinterpret_cast<float4*>(g_gembp + (size_t)blockIdx.x * HRD)[t] = acc;
}

__global__ void final_kernel(const float* __restrict__ pi,
                             const float* __restrict__ pi_w,
                             const float* __restrict__ pi_b,
                             const float* __restrict__ out_w,
                             const float* __restrict__ out_b,
                             float* __restrict__ out) {
    __shared__ float pie[16];
    int b = blockIdx.x, tid = threadIdx.x;
    if (tid < 16) {
        float a = pi_b[tid];
#pragma unroll
        for (int k = 0; k < 25; k++) a = fmaf(pi[b * 25 + k], pi_w[k * 16 + tid], a);
        pie[tid] = fmaxf(a, 0.f);
    }
    __syncthreads();
    int o = tid >> 5, lane = tid & 31;
    float acc = 0.f;
    const float* g0 = g_gembp + (size_t)(b * 4 + 0) * HRD;
    const float* g1 = g_gembp + (size_t)(b * 4 + 1) * HRD;
    const float* g2 = g_gembp + (size_t)(b * 4 + 2) * HRD;
    const float* g3 = g_gembp + (size_t)(b * 4 + 3) * HRD;
    for (int j = lane; j < HRD; j += 32) {
        float ge = (g0[j] + g1[j]) + (g2[j] + g3[j]);
        acc = fmaf(ge, out_w[j * NOUT + o], acc);
    }
    if (lane < 16) acc = fmaf(pie[lane], out_w[(HRD + lane) * NOUT + o], acc);
#pragma unroll
    for (int off = 16; off; off >>= 1) acc += __shfl_down_sync(0xffffffffu, acc, off);
    if (lane == 0) out[b * NOUT + o] = acc + out_b[o];
}

// ---------------- launch -----------------------------------------------------
extern "C" void kernel_launch(void* const* d_in, const int* in_sizes, int n_in,
                              void* d_out, int out_size) {
    const float* x    = (const float*)d_in[0];
    const float* pi   = (const float*)d_in[1];
    const float* eps  = (const float*)d_in[2];
    const float* w1   = (const float*)d_in[3];
    const float* b1   = (const float*)d_in[4];
    const float* bng1 = (const float*)d_in[5];
    const float* bnb1 = (const float*)d_in[6];
    const float* w2   = (const float*)d_in[7];
    const float* b2   = (const float*)d_in[8];
    const float* bng  = (const float*)d_in[9];
    const float* bnb  = (const float*)d_in[10];
    const float* aw   = (const float*)d_in[11];
    const float* ab   = (const float*)d_in[12];
    const float* pw   = (const float*)d_in[13];
    const float* pb   = (const float*)d_in[14];
    const float* ow   = (const float*)d_in[15];
    const float* ob   = (const float*)d_in[16];
    const int*   ei   = (const int*)d_in[17];
    const int*   gid  = (const int*)d_in[18];
    const int* src = ei;
    const int* dst = ei + EE;
    float* out = (float*)d_out;

    cudaFuncSetAttribute(gemm128_kernel<false>,
                         cudaFuncAttributeMaxDynamicSharedMemorySize, GEMM_SMEM);
    cudaFuncSetAttribute(gemm128_kernel<true>,
                         cudaFuncAttributeMaxDynamicSharedMemorySize, GEMM_SMEM);

    const int ELT_BLOCKS = (NN * 32 + 255) / 256;          // 6250
    const int GEMM_BLOCKS = (NN + TILE_R - 1) / TILE_R;    // 313
    const int EDGE_BLK = (EE + 255) / 256;                 // 3125

    // ---- CSR by dst; g_cnt==0 at entry; scan zeroes stats + seeds cursors ----
    hist_kernel<<<EDGE_BLK, 256>>>(dst);                   // launch 1
    scan_kernel<<<1, 1024>>>();                            // launch 2
    scatter_kernel<<<EDGE_BLK, 256>>>(src, dst);           // launch 3

    for (int l = 0; l < LL; l++) {
        aggregate_kernel<<<ELT_BLOCKS, 256>>>(x, eps, l);  // launch 4 (profiled, l=0)
        if (l == 0) copyx_scores_kernel<<<ELT_BLOCKS, 256>>>(x, aw, ab);
        gemm128_kernel<false><<<GEMM_BLOCKS, 256, GEMM_SMEM>>>(
            w1 + (size_t)l * DD * DD, b1 + l * DD, nullptr, nullptr, l);
        gemm128_kernel<true><<<GEMM_BLOCKS, 256, GEMM_SMEM>>>(
            w2 + (size_t)l * DD * DD, b2 + l * DD, bng1 + l * DD, bnb1 + l * DD, l);
        apply_h_kernel<<<ELT_BLOCKS, 256>>>(l, aw, bng + l * DD, bnb + l * DD);
    }

    gemb_part_kernel<<<4 * BB, 256>>>(gid);
    final_kernel<<<BB, 320>>>(pi, pw, pb, ow, ob, out);
}

// round 10
// speedup vs baseline: 2.3529x; 1.4860x over previous
#include <cuda_runtime.h>
#include <math_constants.h>
#include <math.h>

#define NN 50000
#define EE 800000
#define BB 64
#define DD 128
#define LL 4
#define HRD 640      /* D*(L+1) */
#define NOUT 10
#define BN_EPS 1e-5

#define TILE_R 176   /* 285 blocks @ 2/SM = 0.96 waves; proven R5/R6 family */
#define ASTRIDE 132  /* padded smem row stride: rg groups hit distinct banks */
#define RPT (TILE_R / 16)   /* 11 rows per thread */

// ---------------- scratch (device globals; no allocation allowed) ----------
__device__ __align__(16) float  g_hr[(size_t)NN * HRD];   // [x | h1 | h2 | h3 | h4]
__device__ __align__(16) float  g_pooled[NN * DD];
__device__ __align__(16) float  g_z1[NN * DD];
__device__ __align__(16) float  g_z2[NN * DD];
// per-(layer,linear) BN stat slots: [2l] = after mlp_w1, [2l+1] = after mlp_w2
__device__ double g_sumS[2 * LL][DD];
__device__ double g_sumQ[2 * LL][DD];
__device__ float  g_scores[NN];
__device__ __align__(16) float  g_gembp[4 * BB * HRD];    // 4 partials per graph
// CSR scratch. Invariants across calls (graph replays):
//   g_cnt == 0 at call entry (zeroed by scan each call; zero at module load)
//   g_cur is seeded to rowptr by scan each call BEFORE scatter uses it
__device__ int g_cnt[NN];
__device__ int g_cur[NN];
__device__ int g_rowptr[NN + 1];
__device__ int g_esrc[EE];

// ---------------- packed f32x2 helpers (Blackwell) --------------------------
__device__ __forceinline__ void ffma2(unsigned long long& acc,
                                      unsigned long long a,
                                      unsigned long long b) {
    asm("fma.rn.f32x2 %0, %1, %2, %0;" : "+l"(acc) : "l"(a), "l"(b));
}
__device__ __forceinline__ unsigned long long splat2(float a) {
    unsigned long long r;
    asm("mov.b64 %0, {%1, %1};" : "=l"(r) : "f"(a));
    return r;
}
__device__ __forceinline__ float2 unpack2(unsigned long long v) {
    float2 r;
    asm("mov.b64 {%0, %1}, %2;" : "=f"(r.x), "=f"(r.y) : "l"(v));
    return r;
}

// ---------------- CSR construction ------------------------------------------
__global__ void hist_kernel(const int* __restrict__ dst) {
    int e = blockIdx.x * blockDim.x + threadIdx.x;
    if (e < EE) atomicAdd(&g_cnt[dst[e]], 1);
}

// single-block hierarchical scan over 50000 counts.
// Writes rowptr, seeds g_cur = rowptr, zeroes g_cnt, zeroes BN stat slots.
__global__ void __launch_bounds__(1024) scan_kernel() {
    __shared__ int wsum[32];
    __shared__ int carry_sh;
    int tid = threadIdx.x, lane = tid & 31, wid = tid >> 5;
    // zero BN stat slots (deterministic per call -> replay safe)
    for (int i = tid; i < 2 * LL * DD; i += 1024) {
        (&g_sumS[0][0])[i] = 0.0;
        (&g_sumQ[0][0])[i] = 0.0;
    }
    if (tid == 0) carry_sh = 0;
    __syncthreads();
    for (int t = 0; t < 49; t++) {
        int g = t * 1024 + tid;
        int v = (g < NN) ? g_cnt[g] : 0;
        if (g < NN) g_cnt[g] = 0;
        int carry = carry_sh;
        int s = v;
#pragma unroll
        for (int off = 1; off < 32; off <<= 1) {
            int u = __shfl_up_sync(0xffffffffu, s, off);
            if (lane >= off) s += u;
        }
        if (lane == 31) wsum[wid] = s;
        __syncthreads();
        if (wid == 0) {
            int ws = wsum[lane];
#pragma unroll
            for (int off = 1; off < 32; off <<= 1) {
                int u = __shfl_up_sync(0xffffffffu, ws, off);
                if (lane >= off) ws += u;
            }
            wsum[lane] = ws;
        }
        __syncthreads();
        int wpre = (wid == 0) ? 0 : wsum[wid - 1];
        if (g < NN) {
            int rp = carry + wpre + s - v;
            g_rowptr[g] = rp;
            g_cur[g] = rp;          // scatter cursor seeded fresh every call
        }
        __syncthreads();
        if (tid == 1023) carry_sh = carry + wsum[31];
        __syncthreads();
    }
    if (tid == 0) g_rowptr[NN] = EE;
}

__global__ void scatter_kernel(const int* __restrict__ src,
                               const int* __restrict__ dst) {
    int e = blockIdx.x * blockDim.x + threadIdx.x;
    if (e >= EE) return;
    int d = dst[e];
    int p = atomicAdd(&g_cur[d], 1);   // cursor pre-seeded to rowptr[d]
    g_esrc[p] = src[e];
}

// ---------------- aggregation (gather via CSR, high occupancy) ---------------
// pooled[i] = sum_{incoming} h[src] + (1+eps[l])*h[i]
__global__ void aggregate_kernel(const float* __restrict__ x,
                                 const float* __restrict__ eps, int l) {
    int idx = blockIdx.x * blockDim.x + threadIdx.x;
    int i = idx >> 5, lane = idx & 31;
    if (i >= NN) return;
    const float* hsrc = (l == 0) ? x : (g_hr + (size_t)l * DD);
    const int stride = (l == 0) ? DD : HRD;
    int beg = g_rowptr[i], end = g_rowptr[i + 1];
    float4 acc = make_float4(0.f, 0.f, 0.f, 0.f);
    int e = beg;
    for (; e + 3 < end; e += 4) {
        int s0 = g_esrc[e], s1 = g_esrc[e + 1], s2 = g_esrc[e + 2], s3 = g_esrc[e + 3];
        float4 v0 = reinterpret_cast<const float4*>(hsrc + (size_t)s0 * stride)[lane];
        float4 v1 = reinterpret_cast<const float4*>(hsrc + (size_t)s1 * stride)[lane];
        float4 v2 = reinterpret_cast<const float4*>(hsrc + (size_t)s2 * stride)[lane];
        float4 v3 = reinterpret_cast<const float4*>(hsrc + (size_t)s3 * stride)[lane];
        acc.x += (v0.x + v1.x) + (v2.x + v3.x);
        acc.y += (v0.y + v1.y) + (v2.y + v3.y);
        acc.z += (v0.z + v1.z) + (v2.z + v3.z);
        acc.w += (v0.w + v1.w) + (v2.w + v3.w);
    }
    for (; e < end; e++) {
        int s0 = g_esrc[e];
        float4 v0 = reinterpret_cast<const float4*>(hsrc + (size_t)s0 * stride)[lane];
        acc.x += v0.x; acc.y += v0.y; acc.z += v0.z; acc.w += v0.w;
    }
    float sc = 1.0f + eps[l];
    float4 h = reinterpret_cast<const float4*>(hsrc + (size_t)i * stride)[lane];
    acc.x = fmaf(sc, h.x, acc.x);
    acc.y = fmaf(sc, h.y, acc.y);
    acc.z = fmaf(sc, h.z, acc.z);
    acc.w = fmaf(sc, h.w, acc.w);
    reinterpret_cast<float4*>(g_pooled + (size_t)i * DD)[lane] = acc;
}

// ---------------- elementwise / fused score kernels --------------------------
// copy x into hr slab AND initialize scores with x-segment dot
__global__ void copyx_scores_kernel(const float* __restrict__ x,
                                    const float* __restrict__ aw,
                                    const float* __restrict__ ab) {
    int idx = blockIdx.x * blockDim.x + threadIdx.x;
    if (idx >= NN * 32) return;
    int i = idx >> 5, c = idx & 31;
    float4 v = reinterpret_cast<const float4*>(x + (size_t)i * DD)[c];
    reinterpret_cast<float4*>(g_hr + (size_t)i * HRD)[c] = v;
    float4 w = reinterpret_cast<const float4*>(aw)[c];
    float s = v.x * w.x + v.y * w.y + v.z * w.z + v.w * w.w;
#pragma unroll
    for (int off = 16; off; off >>= 1) s += __shfl_down_sync(0xffffffffu, s, off);
    if ((idx & 31) == 0) g_scores[i] = s + ab[0];
}

// h_{l+1} = relu(a*z2 + c) -> hr slab; accumulate score segment.
// Computes BN affine per block from stat slot (2l+1).
__global__ void __launch_bounds__(256) apply_h_kernel(int l,
                                                      const float* __restrict__ aw,
                                                      const float* __restrict__ gamma,
                                                      const float* __restrict__ beta) {
    __shared__ float bnA[DD], bnC[DD];
    int tid = threadIdx.x;
    if (tid < DD) {
        double m = g_sumS[2 * l + 1][tid] / (double)NN;
        double v = g_sumQ[2 * l + 1][tid] / (double)NN - m * m;
        float a = gamma[tid] * rsqrtf((float)(v + (double)BN_EPS));
        bnA[tid] = a;
        bnC[tid] = beta[tid] - (float)m * a;
    }
    __syncthreads();
    int idx = blockIdx.x * blockDim.x + tid;
    if (idx >= NN * 32) return;
    int i = idx >> 5, c = idx & 31;
    float4 z = reinterpret_cast<const float4*>(g_z2 + (size_t)i * DD)[c];
    float4 a = reinterpret_cast<const float4*>(bnA)[c];
    float4 b = reinterpret_cast<const float4*>(bnC)[c];
    float4 o;
    o.x = fmaxf(fmaf(a.x, z.x, b.x), 0.f);
    o.y = fmaxf(fmaf(a.y, z.y, b.y), 0.f);
    o.z = fmaxf(fmaf(a.z, z.z, b.z), 0.f);
    o.w = fmaxf(fmaf(a.w, z.w, b.w), 0.f);
    reinterpret_cast<float4*>(g_hr + (size_t)i * HRD + (size_t)(l + 1) * DD)[c] = o;
    float4 w = reinterpret_cast<const float4*>(aw)[(l + 1) * 32 + c];
    float s = o.x * w.x + o.y * w.y + o.z * w.z + o.w * w.w;
#pragma unroll
    for (int off = 16; off; off >>= 1) s += __shfl_down_sync(0xffffffffu, s, off);
    if ((tid & 31) == 0) g_scores[i] += s;
}

// ---------------- GEMM (176 x 128) @ W[128,128] + b; col stats in fp64 -------
// SECOND=false: A = g_pooled (plain), C = g_z1, stats -> slot 2l
// SECOND=true : A = relu(affine(g_z1)) from slot 2l, C = g_z2, stats -> slot 2l+1
// Mainloop software-pipelines W: next-k LDG issued before current-k FFMA2s.
#define GEMM_SMEM (TILE_R * ASTRIDE * 4 + 2 * DD * 8 + 2 * DD * 4)

template <bool SECOND>
__global__ void __launch_bounds__(256, 2) gemm128_kernel(const float* __restrict__ W,
                                                         const float* __restrict__ bias,
                                                         const float* __restrict__ gamma,
                                                         const float* __restrict__ beta,
                                                         int l) {
    extern __shared__ float smem[];
    float* Ash = smem;                                        // TILE_R x ASTRIDE
    double* redS = reinterpret_cast<double*>(smem + TILE_R * ASTRIDE);
    double* redQ = redS + DD;
    float* bnA = reinterpret_cast<float*>(redQ + DD);
    float* bnC = bnA + DD;

    float* C = SECOND ? g_z2 : g_z1;
    const int slot_out = SECOND ? (2 * l + 1) : (2 * l);

    int tid = threadIdx.x;
    if (tid < DD) {
        redS[tid] = 0.0; redQ[tid] = 0.0;
        if (SECOND) {
            double m = g_sumS[2 * l][tid] / (double)NN;
            double v = g_sumQ[2 * l][tid] / (double)NN - m * m;
            float a = gamma[tid] * rsqrtf((float)(v + (double)BN_EPS));
            bnA[tid] = a;
            bnC[tid] = beta[tid] - (float)m * a;
        }
    }
    __syncthreads();

    int row0 = blockIdx.x * TILE_R;
    {
        const float* A = SECOND ? g_z1 : g_pooled;
#pragma unroll
        for (int ii = 0; ii < TILE_R * 32 / 256; ii++) {
            int i = tid + ii * 256;             // float4 index over tile
            int r = i >> 5, c4 = i & 31;
            int row = row0 + r;
            float4 v = make_float4(0.f, 0.f, 0.f, 0.f);
            if (row < NN) {
                v = *reinterpret_cast<const float4*>(A + (size_t)row * DD + c4 * 4);
                if (SECOND) {
                    float4 ba = reinterpret_cast<const float4*>(bnA)[c4];
                    float4 bc = reinterpret_cast<const float4*>(bnC)[c4];
                    v.x = fmaxf(fmaf(ba.x, v.x, bc.x), 0.f);
                    v.y = fmaxf(fmaf(ba.y, v.y, bc.y), 0.f);
                    v.z = fmaxf(fmaf(ba.z, v.z, bc.z), 0.f);
                    v.w = fmaxf(fmaf(ba.w, v.w, bc.w), 0.f);
                }
            }
            *reinterpret_cast<float4*>(Ash + r * ASTRIDE + c4 * 4) = v;
        }
    }
    __syncthreads();

    int cg = tid & 15;   // 8 columns: 8*cg .. 8*cg+7
    int rg = tid >> 4;   // rows rg*RPT .. rg*RPT+RPT-1
    const float* arow = Ash + rg * RPT * ASTRIDE;
    const ulonglong2* Wg = reinterpret_cast<const ulonglong2*>(W);

    unsigned long long acc[RPT][4];
#pragma unroll
    for (int r = 0; r < RPT; r++)
#pragma unroll
        for (int p = 0; p < 4; p++) acc[r][p] = 0ull;

    // software-pipelined W: prefetch k+1 before computing k
    ulonglong2 wA = __ldg(&Wg[cg * 2]);
    ulonglong2 wB = __ldg(&Wg[cg * 2 + 1]);
#pragma unroll 2
    for (int k = 0; k < DD - 1; k++) {
        ulonglong2 nA = __ldg(&Wg[(k + 1) * 32 + cg * 2]);
        ulonglong2 nB = __ldg(&Wg[(k + 1) * 32 + cg * 2 + 1]);
#pragma unroll
        for (int r = 0; r < RPT; r++) {
            unsigned long long a2 = splat2(arow[r * ASTRIDE + k]);
            ffma2(acc[r][0], a2, wA.x);
            ffma2(acc[r][1], a2, wA.y);
            ffma2(acc[r][2], a2, wB.x);
            ffma2(acc[r][3], a2, wB.y);
        }
        wA = nA; wB = nB;
    }
#pragma unroll
    for (int r = 0; r < RPT; r++) {       // tail k = DD-1
        unsigned long long a2 = splat2(arow[r * ASTRIDE + (DD - 1)]);
        ffma2(acc[r][0], a2, wA.x);
        ffma2(acc[r][1], a2, wA.y);
        ffma2(acc[r][2], a2, wB.x);
        ffma2(acc[r][3], a2, wB.y);
    }

    float bs[8];
#pragma unroll
    for (int j = 0; j < 8; j++) bs[j] = bias[cg * 8 + j];

    float cs[8], cq[8];
#pragma unroll
    for (int j = 0; j < 8; j++) { cs[j] = 0.f; cq[j] = 0.f; }

#pragma unroll
    for (int r = 0; r < RPT; r++) {
        int row = row0 + rg * RPT + r;
        if (row >= NN) continue;
        float o[8];
#pragma unroll
        for (int p = 0; p < 4; p++) {
            float2 u = unpack2(acc[r][p]);
            o[2 * p]     = u.x + bs[2 * p];
            o[2 * p + 1] = u.y + bs[2 * p + 1];
        }
        float4* cp = reinterpret_cast<float4*>(C + (size_t)row * DD + cg * 8);
        cp[0] = make_float4(o[0], o[1], o[2], o[3]);
        cp[1] = make_float4(o[4], o[5], o[6], o[7]);
#pragma unroll
        for (int j = 0; j < 8; j++) {
            cs[j] += o[j];
            cq[j] += o[j] * o[j];
        }
    }
    __syncthreads();
#pragma unroll
    for (int j = 0; j < 8; j++) {
        atomicAdd(&redS[cg * 8 + j], (double)cs[j]);
        atomicAdd(&redQ[cg * 8 + j], (double)cq[j]);
    }
    __syncthreads();
    if (tid < DD) {
        atomicAdd(&g_sumS[slot_out][tid], redS[tid]);
        atomicAdd(&g_sumQ[slot_out][tid], redQ[tid]);
    }
}

// ---------------- attention pooling + head ----------------------------------
// 4 blocks per graph; each computes segment max+denom (redundant, cheap) and
// its quarter of the weighted sum. Atomic-free.
#define ECHUNK 512
__global__ void __launch_bounds__(256) gemb_part_kernel(const int* __restrict__ gid) {
    __shared__ int s_beg, s_end;
    __shared__ float red[32];
    __shared__ float s_mx, s_dn;
    __shared__ float ecache[ECHUNK];
    int b = blockIdx.x >> 2, q = blockIdx.x & 3, t = threadIdx.x;
    int lane = t & 31, wid = t >> 5;
    if (t == 0) {
        int lo = 0, hi = NN;
        while (lo < hi) { int m = (lo + hi) >> 1; if (gid[m] < b) lo = m + 1; else hi = m; }
        s_beg = lo;
        lo = 0; hi = NN;
        while (lo < hi) { int m = (lo + hi) >> 1; if (gid[m] < b + 1) lo = m + 1; else hi = m; }
        s_end = lo;
    }
    __syncthreads();
    int beg = s_beg, end = s_end;

    float mx = -CUDART_INF_F;
    for (int i = beg + t; i < end; i += 256) mx = fmaxf(mx, g_scores[i]);
#pragma unroll
    for (int off = 16; off; off >>= 1) mx = fmaxf(mx, __shfl_xor_sync(0xffffffffu, mx, off));
    if (lane == 0) red[wid] = mx;
    __syncthreads();
    if (wid == 0) {
        float m2 = (lane < 8) ? red[lane] : -CUDART_INF_F;
#pragma unroll
        for (int off = 4; off; off >>= 1) m2 = fmaxf(m2, __shfl_xor_sync(0xffffffffu, m2, off));
        if (lane == 0) s_mx = m2;
    }
    __syncthreads();
    float smax = s_mx;

    float dn = 0.f;
    for (int i = beg + t; i < end; i += 256) dn += expf(g_scores[i] - smax);
#pragma unroll
    for (int off = 16; off; off >>= 1) dn += __shfl_xor_sync(0xffffffffu, dn, off);
    if (lane == 0) red[wid] = dn;
    __syncthreads();
    if (wid == 0) {
        float d2 = (lane < 8) ? red[lane] : 0.f;
#pragma unroll
        for (int off = 4; off; off >>= 1) d2 += __shfl_xor_sync(0xffffffffu, d2, off);
        if (lane == 0) s_dn = d2;
    }
    __syncthreads();
    float denom = s_dn;

    int len = end - beg;
    int qb = beg + (int)(((long long)len * q) >> 2);
    int qe = beg + (int)(((long long)len * (q + 1)) >> 2);

    float4 acc = make_float4(0.f, 0.f, 0.f, 0.f);
    for (int chunk = qb; chunk < qe; chunk += ECHUNK) {
        int ce = chunk + ECHUNK < qe ? chunk + ECHUNK : qe;
        for (int i = chunk + t; i < ce; i += 256)
            ecache[i - chunk] = expf(g_scores[i] - smax) / denom;
        __syncthreads();
        if (t < HRD / 4) {
            for (int i = chunk; i < ce; i++) {
                float c = ecache[i - chunk];
                float4 v = reinterpret_cast<const float4*>(g_hr + (size_t)i * HRD)[t];
                acc.x = fmaf(c, v.x, acc.x);
                acc.y = fmaf(c, v.y, acc.y);
                acc.z = fmaf(c, v.z, acc.z);
                acc.w = fmaf(c, v.w, acc.w);
            }
        }
        __syncthreads();
    }
    if (t < HRD / 4)
        reinterpret_cast<float4*>(g_gembp + (size_t)blockIdx.x * HRD)[t] = acc;
}

__global__ void final_kernel(const float* __restrict__ pi,
                             const float* __restrict__ pi_w,
                             const float* __restrict__ pi_b,
                             const float* __restrict__ out_w,
                             const float* __restrict__ out_b,
                             float* __restrict__ out) {
    __shared__ float pie[16];
    int b = blockIdx.x, tid = threadIdx.x;
    if (tid < 16) {
        float a = pi_b[tid];
#pragma unroll
        for (int k = 0; k < 25; k++) a = fmaf(pi[b * 25 + k], pi_w[k * 16 + tid], a);
        pie[tid] = fmaxf(a, 0.f);
    }
    __syncthreads();
    int o = tid >> 5, lane = tid & 31;
    float acc = 0.f;
    const float* g0 = g_gembp + (size_t)(b * 4 + 0) * HRD;
    const float* g1 = g_gembp + (size_t)(b * 4 + 1) * HRD;
    const float* g2 = g_gembp + (size_t)(b * 4 + 2) * HRD;
    const float* g3 = g_gembp + (size_t)(b * 4 + 3) * HRD;
    for (int j = lane; j < HRD; j += 32) {
        float ge = (g0[j] + g1[j]) + (g2[j] + g3[j]);
        acc = fmaf(ge, out_w[j * NOUT + o], acc);
    }
    if (lane < 16) acc = fmaf(pie[lane], out_w[(HRD + lane) * NOUT + o], acc);
#pragma unroll
    for (int off = 16; off; off >>= 1) acc += __shfl_down_sync(0xffffffffu, acc, off);
    if (lane == 0) out[b * NOUT + o] = acc + out_b[o];
}

// ---------------- launch -----------------------------------------------------
extern "C" void kernel_launch(void* const* d_in, const int* in_sizes, int n_in,
                              void* d_out, int out_size) {
    const float* x    = (const float*)d_in[0];
    const float* pi   = (const float*)d_in[1];
    const float* eps  = (const float*)d_in[2];
    const float* w1   = (const float*)d_in[3];
    const float* b1   = (const float*)d_in[4];
    const float* bng1 = (const float*)d_in[5];
    const float* bnb1 = (const float*)d_in[6];
    const float* w2   = (const float*)d_in[7];
    const float* b2   = (const float*)d_in[8];
    const float* bng  = (const float*)d_in[9];
    const float* bnb  = (const float*)d_in[10];
    const float* aw   = (const float*)d_in[11];
    const float* ab   = (const float*)d_in[12];
    const float* pw   = (const float*)d_in[13];
    const float* pb   = (const float*)d_in[14];
    const float* ow   = (const float*)d_in[15];
    const float* ob   = (const float*)d_in[16];
    const int*   ei   = (const int*)d_in[17];
    const int*   gid  = (const int*)d_in[18];
    const int* src = ei;
    const int* dst = ei + EE;
    float* out = (float*)d_out;

    cudaFuncSetAttribute(gemm128_kernel<false>,
                         cudaFuncAttributeMaxDynamicSharedMemorySize, GEMM_SMEM);
    cudaFuncSetAttribute(gemm128_kernel<true>,
                         cudaFuncAttributeMaxDynamicSharedMemorySize, GEMM_SMEM);

    const int ELT_BLOCKS = (NN * 32 + 255) / 256;          // 6250
    const int GEMM_BLOCKS = (NN + TILE_R - 1) / TILE_R;    // 285
    const int EDGE_BLK = (EE + 255) / 256;                 // 3125

    // ---- CSR by dst; g_cnt==0 at entry; scan zeroes stats + seeds cursors ----
    hist_kernel<<<EDGE_BLK, 256>>>(dst);                   // launch 1
    scan_kernel<<<1, 1024>>>();                            // launch 2
    scatter_kernel<<<EDGE_BLK, 256>>>(src, dst);           // launch 3

    for (int l = 0; l < LL; l++) {
        aggregate_kernel<<<ELT_BLOCKS, 256>>>(x, eps, l);  // launch 4 (profiled, l=0)
        if (l == 0) copyx_scores_kernel<<<ELT_BLOCKS, 256>>>(x, aw, ab);
        gemm128_kernel<false><<<GEMM_BLOCKS, 256, GEMM_SMEM>>>(
            w1 + (size_t)l * DD * DD, b1 + l * DD, nullptr, nullptr, l);
        gemm128_kernel<true><<<GEMM_BLOCKS, 256, GEMM_SMEM>>>(
            w2 + (size_t)l * DD * DD, b2 + l * DD, bng1 + l * DD, bnb1 + l * DD, l);
        apply_h_kernel<<<ELT_BLOCKS, 256>>>(l, aw, bng + l * DD, bnb + l * DD);
    }

    gemb_part_kernel<<<4 * BB, 256>>>(gid);
    final_kernel<<<BB, 320>>>(pi, pw, pb, ow, ob, out);
}

// round 11
// speedup vs baseline: 2.3700x; 1.0073x over previous
#include <cuda_runtime.h>
#include <math_constants.h>
#include <math.h>

#define NN 50000
#define EE 800000
#define BB 64
#define DD 128
#define LL 4
#define HRD 640      /* D*(L+1) */
#define NOUT 10
#define BN_EPS 1e-5

#define TILE_R 176   /* 285 blocks @ 2/SM = 0.96 waves; proven family */
#define ASTRIDE 132  /* padded smem row stride: rg groups hit distinct banks */
#define RPT (TILE_R / 16)   /* 11 rows per thread */

// ---------------- scratch (device globals; no allocation allowed) ----------
__device__ __align__(16) float  g_hr[(size_t)NN * HRD];   // [x | h1 | h2 | h3 | h4]
__device__ __align__(16) float  g_pooled[NN * DD];
__device__ __align__(16) float  g_z1[NN * DD];
__device__ __align__(16) float  g_z2[NN * DD];
// per-(layer,linear) BN stat slots: [2l] = after mlp_w1, [2l+1] = after mlp_w2
__device__ double g_sumS[2 * LL][DD];
__device__ double g_sumQ[2 * LL][DD];
__device__ float  g_scores[NN];
__device__ __align__(16) float  g_gembp[4 * BB * HRD];    // 4 partials per graph
// CSR scratch. Invariants across calls (graph replays):
//   g_cnt == 0 at call entry (zeroed by scan each call; zero at module load)
//   g_cur is seeded to rowptr by scan each call BEFORE scatter uses it
__device__ int g_cnt[NN];
__device__ int g_cur[NN];
__device__ int g_rowptr[NN + 1];
__device__ int g_esrc[EE];

// ---------------- packed f32x2 helpers (Blackwell) --------------------------
__device__ __forceinline__ void ffma2(unsigned long long& acc,
                                      unsigned long long a,
                                      unsigned long long b) {
    asm("fma.rn.f32x2 %0, %1, %2, %0;" : "+l"(acc) : "l"(a), "l"(b));
}
__device__ __forceinline__ unsigned long long splat2(float a) {
    unsigned long long r;
    asm("mov.b64 %0, {%1, %1};" : "=l"(r) : "f"(a));
    return r;
}
__device__ __forceinline__ float2 unpack2(unsigned long long v) {
    float2 r;
    asm("mov.b64 {%0, %1}, %2;" : "=f"(r.x), "=f"(r.y) : "l"(v));
    return r;
}

// ---------------- CSR construction ------------------------------------------
__global__ void hist_kernel(const int* __restrict__ dst) {
    int e = blockIdx.x * blockDim.x + threadIdx.x;
    if (e < EE) atomicAdd(&g_cnt[dst[e]], 1);
}

// single-block hierarchical scan over 50000 counts.
// Writes rowptr, seeds g_cur = rowptr, zeroes g_cnt, zeroes BN stat slots.
__global__ void __launch_bounds__(1024) scan_kernel() {
    __shared__ int wsum[32];
    __shared__ int carry_sh;
    int tid = threadIdx.x, lane = tid & 31, wid = tid >> 5;
    // zero BN stat slots (deterministic per call -> replay safe)
    for (int i = tid; i < 2 * LL * DD; i += 1024) {
        (&g_sumS[0][0])[i] = 0.0;
        (&g_sumQ[0][0])[i] = 0.0;
    }
    if (tid == 0) carry_sh = 0;
    __syncthreads();
    for (int t = 0; t < 49; t++) {
        int g = t * 1024 + tid;
        int v = (g < NN) ? g_cnt[g] : 0;
        if (g < NN) g_cnt[g] = 0;
        int carry = carry_sh;
        int s = v;
#pragma unroll
        for (int off = 1; off < 32; off <<= 1) {
            int u = __shfl_up_sync(0xffffffffu, s, off);
            if (lane >= off) s += u;
        }
        if (lane == 31) wsum[wid] = s;
        __syncthreads();
        if (wid == 0) {
            int ws = wsum[lane];
#pragma unroll
            for (int off = 1; off < 32; off <<= 1) {
                int u = __shfl_up_sync(0xffffffffu, ws, off);
                if (lane >= off) ws += u;
            }
            wsum[lane] = ws;
        }
        __syncthreads();
        int wpre = (wid == 0) ? 0 : wsum[wid - 1];
        if (g < NN) {
            int rp = carry + wpre + s - v;
            g_rowptr[g] = rp;
            g_cur[g] = rp;          // scatter cursor seeded fresh every call
        }
        __syncthreads();
        if (tid == 1023) carry_sh = carry + wsum[31];
        __syncthreads();
    }
    if (tid == 0) g_rowptr[NN] = EE;
}

__global__ void scatter_kernel(const int* __restrict__ src,
                               const int* __restrict__ dst) {
    int e = blockIdx.x * blockDim.x + threadIdx.x;
    if (e >= EE) return;
    int d = dst[e];
    int p = atomicAdd(&g_cur[d], 1);   // cursor pre-seeded to rowptr[d]
    g_esrc[p] = src[e];
}

// ---------------- fused aggregation ------------------------------------------
// aggregate<SLAB>:
//   SLAB==0: h = x (passthrough).   SLAB>=1: h = relu(bnA*z2 + bnC) on the fly
//   (bn affine from stat slot 2*(SLAB-1)+1 + gamma/beta of layer SLAB-1).
// For node i: pooled[i] = sum_nbr h[src] + (1+eps[SLAB])*h[i];
// writes h[i] into hr slab SLAB; accumulates attention score segment.
template <int SLAB>
__global__ void __launch_bounds__(256) aggregate_kernel(
    const float* __restrict__ x, const float* __restrict__ eps,
    const float* __restrict__ aw, const float* __restrict__ ab,
    const float* __restrict__ gamma, const float* __restrict__ beta) {
    __shared__ float bnA[DD], bnC[DD];
    int tid = threadIdx.x;
    if (SLAB > 0) {
        if (tid < DD) {
            double m = g_sumS[2 * (SLAB - 1) + 1][tid] / (double)NN;
            double v = g_sumQ[2 * (SLAB - 1) + 1][tid] / (double)NN - m * m;
            float a = gamma[tid] * rsqrtf((float)(v + (double)BN_EPS));
            bnA[tid] = a;
            bnC[tid] = beta[tid] - (float)m * a;
        }
        __syncthreads();
    }
    int idx = blockIdx.x * 256 + tid;
    int i = idx >> 5, lane = idx & 31;
    if (i >= NN) return;

    float4 a4, c4;
    if (SLAB > 0) {
        a4 = reinterpret_cast<const float4*>(bnA)[lane];
        c4 = reinterpret_cast<const float4*>(bnC)[lane];
    }
    const float* hsrc = (SLAB == 0) ? x : g_z2;

    auto loadh = [&](int s) -> float4 {
        float4 v = reinterpret_cast<const float4*>(hsrc + (size_t)s * DD)[lane];
        if (SLAB > 0) {
            v.x = fmaxf(fmaf(a4.x, v.x, c4.x), 0.f);
            v.y = fmaxf(fmaf(a4.y, v.y, c4.y), 0.f);
            v.z = fmaxf(fmaf(a4.z, v.z, c4.z), 0.f);
            v.w = fmaxf(fmaf(a4.w, v.w, c4.w), 0.f);
        }
        return v;
    };

    int beg = g_rowptr[i], end = g_rowptr[i + 1];
    float4 acc = make_float4(0.f, 0.f, 0.f, 0.f);
    int e = beg;
    for (; e + 3 < end; e += 4) {
        int s0 = g_esrc[e], s1 = g_esrc[e + 1], s2 = g_esrc[e + 2], s3 = g_esrc[e + 3];
        float4 v0 = loadh(s0), v1 = loadh(s1), v2 = loadh(s2), v3 = loadh(s3);
        acc.x += (v0.x + v1.x) + (v2.x + v3.x);
        acc.y += (v0.y + v1.y) + (v2.y + v3.y);
        acc.z += (v0.z + v1.z) + (v2.z + v3.z);
        acc.w += (v0.w + v1.w) + (v2.w + v3.w);
    }
    for (; e < end; e++) {
        float4 v0 = loadh(g_esrc[e]);
        acc.x += v0.x; acc.y += v0.y; acc.z += v0.z; acc.w += v0.w;
    }

    // self term: h_i, hr-slab write, score segment, pooled
    float4 h = loadh(i);
    reinterpret_cast<float4*>(g_hr + (size_t)i * HRD + (size_t)SLAB * DD)[lane] = h;
    float4 w = reinterpret_cast<const float4*>(aw)[SLAB * 32 + lane];
    float s = h.x * w.x + h.y * w.y + h.z * w.z + h.w * w.w;
#pragma unroll
    for (int off = 16; off; off >>= 1) s += __shfl_down_sync(0xffffffffu, s, off);
    if (lane == 0) {
        if (SLAB == 0) g_scores[i] = s + ab[0];
        else           g_scores[i] += s;
    }
    float sc = 1.0f + eps[SLAB];
    acc.x = fmaf(sc, h.x, acc.x);
    acc.y = fmaf(sc, h.y, acc.y);
    acc.z = fmaf(sc, h.z, acc.z);
    acc.w = fmaf(sc, h.w, acc.w);
    reinterpret_cast<float4*>(g_pooled + (size_t)i * DD)[lane] = acc;
}

// h_4 = relu(affine(z2)) -> hr slab 4; accumulate final score segment (l=3 only)
__global__ void __launch_bounds__(256) apply_h_kernel(int l,
                                                      const float* __restrict__ aw,
                                                      const float* __restrict__ gamma,
                                                      const float* __restrict__ beta) {
    __shared__ float bnA[DD], bnC[DD];
    int tid = threadIdx.x;
    if (tid < DD) {
        double m = g_sumS[2 * l + 1][tid] / (double)NN;
        double v = g_sumQ[2 * l + 1][tid] / (double)NN - m * m;
        float a = gamma[tid] * rsqrtf((float)(v + (double)BN_EPS));
        bnA[tid] = a;
        bnC[tid] = beta[tid] - (float)m * a;
    }
    __syncthreads();
    int idx = blockIdx.x * blockDim.x + tid;
    if (idx >= NN * 32) return;
    int i = idx >> 5, c = idx & 31;
    float4 z = reinterpret_cast<const float4*>(g_z2 + (size_t)i * DD)[c];
    float4 a = reinterpret_cast<const float4*>(bnA)[c];
    float4 b = reinterpret_cast<const float4*>(bnC)[c];
    float4 o;
    o.x = fmaxf(fmaf(a.x, z.x, b.x), 0.f);
    o.y = fmaxf(fmaf(a.y, z.y, b.y), 0.f);
    o.z = fmaxf(fmaf(a.z, z.z, b.z), 0.f);
    o.w = fmaxf(fmaf(a.w, z.w, b.w), 0.f);
    reinterpret_cast<float4*>(g_hr + (size_t)i * HRD + (size_t)(l + 1) * DD)[c] = o;
    float4 w = reinterpret_cast<const float4*>(aw)[(l + 1) * 32 + c];
    float s = o.x * w.x + o.y * w.y + o.z * w.z + o.w * w.w;
#pragma unroll
    for (int off = 16; off; off >>= 1) s += __shfl_down_sync(0xffffffffu, s, off);
    if ((tid & 31) == 0) g_scores[i] += s;
}

// ---------------- GEMM (176 x 128) @ W[128,128] + b; col stats in fp64 -------
// SECOND=false: A = g_pooled (plain), C = g_z1, stats -> slot 2l
// SECOND=true : A = relu(affine(g_z1)) from slot 2l, C = g_z2, stats -> slot 2l+1
// Mainloop software-pipelines W: next-k LDG issued before current-k FFMA2s.
#define GEMM_SMEM (TILE_R * ASTRIDE * 4 + 2 * DD * 8 + 2 * DD * 4)

template <bool SECOND>
__global__ void __launch_bounds__(256, 2) gemm128_kernel(const float* __restrict__ W,
                                                         const float* __restrict__ bias,
                                                         const float* __restrict__ gamma,
                                                         const float* __restrict__ beta,
                                                         int l) {
    extern __shared__ float smem[];
    float* Ash = smem;                                        // TILE_R x ASTRIDE
    double* redS = reinterpret_cast<double*>(smem + TILE_R * ASTRIDE);
    double* redQ = redS + DD;
    float* bnA = reinterpret_cast<float*>(redQ + DD);
    float* bnC = bnA + DD;

    float* C = SECOND ? g_z2 : g_z1;
    const int slot_out = SECOND ? (2 * l + 1) : (2 * l);

    int tid = threadIdx.x;
    if (tid < DD) {
        redS[tid] = 0.0; redQ[tid] = 0.0;
        if (SECOND) {
            double m = g_sumS[2 * l][tid] / (double)NN;
            double v = g_sumQ[2 * l][tid] / (double)NN - m * m;
            float a = gamma[tid] * rsqrtf((float)(v + (double)BN_EPS));
            bnA[tid] = a;
            bnC[tid] = beta[tid] - (float)m * a;
        }
    }
    __syncthreads();

    int row0 = blockIdx.x * TILE_R;
    {
        const float* A = SECOND ? g_z1 : g_pooled;
#pragma unroll
        for (int ii = 0; ii < TILE_R * 32 / 256; ii++) {
            int i = tid + ii * 256;             // float4 index over tile
            int r = i >> 5, c4 = i & 31;
            int row = row0 + r;
            float4 v = make_float4(0.f, 0.f, 0.f, 0.f);
            if (row < NN) {
                v = *reinterpret_cast<const float4*>(A + (size_t)row * DD + c4 * 4);
                if (SECOND) {
                    float4 ba = reinterpret_cast<const float4*>(bnA)[c4];
                    float4 bc = reinterpret_cast<const float4*>(bnC)[c4];
                    v.x = fmaxf(fmaf(ba.x, v.x, bc.x), 0.f);
                    v.y = fmaxf(fmaf(ba.y, v.y, bc.y), 0.f);
                    v.z = fmaxf(fmaf(ba.z, v.z, bc.z), 0.f);
                    v.w = fmaxf(fmaf(ba.w, v.w, bc.w), 0.f);
                }
            }
            *reinterpret_cast<float4*>(Ash + r * ASTRIDE + c4 * 4) = v;
        }
    }
    __syncthreads();

    int cg = tid & 15;   // 8 columns: 8*cg .. 8*cg+7
    int rg = tid >> 4;   // rows rg*RPT .. rg*RPT+RPT-1
    const float* arow = Ash + rg * RPT * ASTRIDE;
    const ulonglong2* Wg = reinterpret_cast<const ulonglong2*>(W);

    unsigned long long acc[RPT][4];
#pragma unroll
    for (int r = 0; r < RPT; r++)
#pragma unroll
        for (int p = 0; p < 4; p++) acc[r][p] = 0ull;

    // software-pipelined W: prefetch k+1 before computing k
    ulonglong2 wA = __ldg(&Wg[cg * 2]);
    ulonglong2 wB = __ldg(&Wg[cg * 2 + 1]);
#pragma unroll 2
    for (int k = 0; k < DD - 1; k++) {
        ulonglong2 nA = __ldg(&Wg[(k + 1) * 32 + cg * 2]);
        ulonglong2 nB = __ldg(&Wg[(k + 1) * 32 + cg * 2 + 1]);
#pragma unroll
        for (int r = 0; r < RPT; r++) {
            unsigned long long a2 = splat2(arow[r * ASTRIDE + k]);
            ffma2(acc[r][0], a2, wA.x);
            ffma2(acc[r][1], a2, wA.y);
            ffma2(acc[r][2], a2, wB.x);
            ffma2(acc[r][3], a2, wB.y);
        }
        wA = nA; wB = nB;
    }
#pragma unroll
    for (int r = 0; r < RPT; r++) {       // tail k = DD-1
        unsigned long long a2 = splat2(arow[r * ASTRIDE + (DD - 1)]);
        ffma2(acc[r][0], a2, wA.x);
        ffma2(acc[r][1], a2, wA.y);
        ffma2(acc[r][2], a2, wB.x);
        ffma2(acc[r][3], a2, wB.y);
    }

    float bs[8];
#pragma unroll
    for (int j = 0; j < 8; j++) bs[j] = bias[cg * 8 + j];

    float cs[8], cq[8];
#pragma unroll
    for (int j = 0; j < 8; j++) { cs[j] = 0.f; cq[j] = 0.f; }

#pragma unroll
    for (int r = 0; r < RPT; r++) {
        int row = row0 + rg * RPT + r;
        if (row >= NN) continue;
        float o[8];
#pragma unroll
        for (int p = 0; p < 4; p++) {
            float2 u = unpack2(acc[r][p]);
            o[2 * p]     = u.x + bs[2 * p];
            o[2 * p + 1] = u.y + bs[2 * p + 1];
        }
        float4* cp = reinterpret_cast<float4*>(C + (size_t)row * DD + cg * 8);
        cp[0] = make_float4(o[0], o[1], o[2], o[3]);
        cp[1] = make_float4(o[4], o[5], o[6], o[7]);
#pragma unroll
        for (int j = 0; j < 8; j++) {
            cs[j] += o[j];
            cq[j] += o[j] * o[j];
        }
    }
    __syncthreads();
#pragma unroll
    for (int j = 0; j < 8; j++) {
        atomicAdd(&redS[cg * 8 + j], (double)cs[j]);
        atomicAdd(&redQ[cg * 8 + j], (double)cq[j]);
    }
    __syncthreads();
    if (tid < DD) {
        atomicAdd(&g_sumS[slot_out][tid], redS[tid]);
        atomicAdd(&g_sumQ[slot_out][tid], redQ[tid]);
    }
}

// ---------------- attention pooling + head ----------------------------------
// 4 blocks per graph; each computes segment max+denom (redundant, cheap) and
// its quarter of the weighted sum. Atomic-free.
#define ECHUNK 512
__global__ void __launch_bounds__(256) gemb_part_kernel(const int* __restrict__ gid) {
    __shared__ int s_beg, s_end;
    __shared__ float red[32];
    __shared__ float s_mx, s_dn;
    __shared__ float ecache[ECHUNK];
    int b = blockIdx.x >> 2, q = blockIdx.x & 3, t = threadIdx.x;
    int lane = t & 31, wid = t >> 5;
    if (t == 0) {
        int lo = 0, hi = NN;
        while (lo < hi) { int m = (lo + hi) >> 1; if (gid[m] < b) lo = m + 1; else hi = m; }
        s_beg = lo;
        lo = 0; hi = NN;
        while (lo < hi) { int m = (lo + hi) >> 1; if (gid[m] < b + 1) lo = m + 1; else hi = m; }
        s_end = lo;
    }
    __syncthreads();
    int beg = s_beg, end = s_end;

    float mx = -CUDART_INF_F;
    for (int i = beg + t; i < end; i += 256) mx = fmaxf(mx, g_scores[i]);
#pragma unroll
    for (int off = 16; off; off >>= 1) mx = fmaxf(mx, __shfl_xor_sync(0xffffffffu, mx, off));
    if (lane == 0) red[wid] = mx;
    __syncthreads();
    if (wid == 0) {
        float m2 = (lane < 8) ? red[lane] : -CUDART_INF_F;
#pragma unroll
        for (int off = 4; off; off >>= 1) m2 = fmaxf(m2, __shfl_xor_sync(0xffffffffu, m2, off));
        if (lane == 0) s_mx = m2;
    }
    __syncthreads();
    float smax = s_mx;

    float dn = 0.f;
    for (int i = beg + t; i < end; i += 256) dn += expf(g_scores[i] - smax);
#pragma unroll
    for (int off = 16; off; off >>= 1) dn += __shfl_xor_sync(0xffffffffu, dn, off);
    if (lane == 0) red[wid] = dn;
    __syncthreads();
    if (wid == 0) {
        float d2 = (lane < 8) ? red[lane] : 0.f;
#pragma unroll
        for (int off = 4; off; off >>= 1) d2 += __shfl_xor_sync(0xffffffffu, d2, off);
        if (lane == 0) s_dn = d2;
    }
    __syncthreads();
    float denom = s_dn;

    int len = end - beg;
    int qb = beg + (int)(((long long)len * q) >> 2);
    int qe = beg + (int)(((long long)len * (q + 1)) >> 2);

    float4 acc = make_float4(0.f, 0.f, 0.f, 0.f);
    for (int chunk = qb; chunk < qe; chunk += ECHUNK) {
        int ce = chunk + ECHUNK < qe ? chunk + ECHUNK : qe;
        for (int i = chunk + t; i < ce; i += 256)
            ecache[i - chunk] = expf(g_scores[i] - smax) / denom;
        __syncthreads();
        if (t < HRD / 4) {
            for (int i = chunk; i < ce; i++) {
                float c = ecache[i - chunk];
                float4 v = reinterpret_cast<const float4*>(g_hr + (size_t)i * HRD)[t];
                acc.x = fmaf(c, v.x, acc.x);
                acc.y = fmaf(c, v.y, acc.y);
                acc.z = fmaf(c, v.z, acc.z);
                acc.w = fmaf(c, v.w, acc.w);
            }
        }
        __syncthreads();
    }
    if (t < HRD / 4)
        reinterpret_cast<float4*>(g_gembp + (size_t)blockIdx.x * HRD)[t] = acc;
}

__global__ void final_kernel(const float* __restrict__ pi,
                             const float* __restrict__ pi_w,
                             const float* __restrict__ pi_b,
                             const float* __restrict__ out_w,
                             const float* __restrict__ out_b,
                             float* __restrict__ out) {
    __shared__ float pie[16];
    int b = blockIdx.x, tid = threadIdx.x;
    if (tid < 16) {
        float a = pi_b[tid];
#pragma unroll
        for (int k = 0; k < 25; k++) a = fmaf(pi[b * 25 + k], pi_w[k * 16 + tid], a);
        pie[tid] = fmaxf(a, 0.f);
    }
    __syncthreads();
    int o = tid >> 5, lane = tid & 31;
    float acc = 0.f;
    const float* g0 = g_gembp + (size_t)(b * 4 + 0) * HRD;
    const float* g1 = g_gembp + (size_t)(b * 4 + 1) * HRD;
    const float* g2 = g_gembp + (size_t)(b * 4 + 2) * HRD;
    const float* g3 = g_gembp + (size_t)(b * 4 + 3) * HRD;
    for (int j = lane; j < HRD; j += 32) {
        float ge = (g0[j] + g1[j]) + (g2[j] + g3[j]);
        acc = fmaf(ge, out_w[j * NOUT + o], acc);
    }
    if (lane < 16) acc = fmaf(pie[lane], out_w[(HRD + lane) * NOUT + o], acc);
#pragma unroll
    for (int off = 16; off; off >>= 1) acc += __shfl_down_sync(0xffffffffu, acc, off);
    if (lane == 0) out[b * NOUT + o] = acc + out_b[o];
}

// ---------------- launch -----------------------------------------------------
extern "C" void kernel_launch(void* const* d_in, const int* in_sizes, int n_in,
                              void* d_out, int out_size) {
    const float* x    = (const float*)d_in[0];
    const float* pi   = (const float*)d_in[1];
    const float* eps  = (const float*)d_in[2];
    const float* w1   = (const float*)d_in[3];
    const float* b1   = (const float*)d_in[4];
    const float* bng1 = (const float*)d_in[5];
    const float* bnb1 = (const float*)d_in[6];
    const float* w2   = (const float*)d_in[7];
    const float* b2   = (const float*)d_in[8];
    const float* bng  = (const float*)d_in[9];
    const float* bnb  = (const float*)d_in[10];
    const float* aw   = (const float*)d_in[11];
    const float* ab   = (const float*)d_in[12];
    const float* pw   = (const float*)d_in[13];
    const float* pb   = (const float*)d_in[14];
    const float* ow   = (const float*)d_in[15];
    const float* ob   = (const float*)d_in[16];
    const int*   ei   = (const int*)d_in[17];
    const int*   gid  = (const int*)d_in[18];
    const int* src = ei;
    const int* dst = ei + EE;
    float* out = (float*)d_out;

    cudaFuncSetAttribute(gemm128_kernel<false>,
                         cudaFuncAttributeMaxDynamicSharedMemorySize, GEMM_SMEM);
    cudaFuncSetAttribute(gemm128_kernel<true>,
                         cudaFuncAttributeMaxDynamicSharedMemorySize, GEMM_SMEM);

    const int ELT_BLOCKS = (NN * 32 + 255) / 256;          // 6250
    const int GEMM_BLOCKS = (NN + TILE_R - 1) / TILE_R;    // 285
    const int EDGE_BLK = (EE + 255) / 256;                 // 3125

    // ---- CSR by dst; g_cnt==0 at entry; scan zeroes stats + seeds cursors ----
    hist_kernel<<<EDGE_BLK, 256>>>(dst);                   // launch 1
    scan_kernel<<<1, 1024>>>();                            // launch 2
    scatter_kernel<<<EDGE_BLK, 256>>>(src, dst);           // launch 3

    // layer 0
    aggregate_kernel<0><<<ELT_BLOCKS, 256>>>(x, eps, aw, ab, nullptr, nullptr); // launch 4 (profiled)
    gemm128_kernel<false><<<GEMM_BLOCKS, 256, GEMM_SMEM>>>(w1, b1, nullptr, nullptr, 0);
    gemm128_kernel<true><<<GEMM_BLOCKS, 256, GEMM_SMEM>>>(w2, b2, bng1, bnb1, 0);
    // layer 1
    aggregate_kernel<1><<<ELT_BLOCKS, 256>>>(x, eps, aw, ab, bng + 0 * DD, bnb + 0 * DD);
    gemm128_kernel<false><<<GEMM_BLOCKS, 256, GEMM_SMEM>>>(w1 + 1 * DD * DD, b1 + 1 * DD, nullptr, nullptr, 1);
    gemm128_kernel<true><<<GEMM_BLOCKS, 256, GEMM_SMEM>>>(w2 + 1 * DD * DD, b2 + 1 * DD, bng1 + 1 * DD, bnb1 + 1 * DD, 1);
    // layer 2
    aggregate_kernel<2><<<ELT_BLOCKS, 256>>>(x, eps, aw, ab, bng + 1 * DD, bnb + 1 * DD);
    gemm128_kernel<false><<<GEMM_BLOCKS, 256, GEMM_SMEM>>>(w1 + 2 * DD * DD, b1 + 2 * DD, nullptr, nullptr, 2);
    gemm128_kernel<true><<<GEMM_BLOCKS, 256, GEMM_SMEM>>>(w2 + 2 * DD * DD, b2 + 2 * DD, bng1 + 2 * DD, bnb1 + 2 * DD, 2);
    // layer 3
    aggregate_kernel<3><<<ELT_BLOCKS, 256>>>(x, eps, aw, ab, bng + 2 * DD, bnb + 2 * DD);
    gemm128_kernel<false><<<GEMM_BLOCKS, 256, GEMM_SMEM>>>(w1 + 3 * DD * DD, b1 + 3 * DD, nullptr, nullptr, 3);
    gemm128_kernel<true><<<GEMM_BLOCKS, 256, GEMM_SMEM>>>(w2 + 3 * DD * DD, b2 + 3 * DD, bng1 + 3 * DD, bnb1 + 3 * DD, 3);
    // slab 4 (h_4) + final score segment
    apply_h_kernel<<<ELT_BLOCKS, 256>>>(3, aw, bng + 3 * DD, bnb + 3 * DD);

    gemb_part_kernel<<<4 * BB, 256>>>(gid);
    final_kernel<<<BB, 320>>>(pi, pw, pb, ow, ob, out);
}